// round 9
// baseline (speedup 1.0000x reference)
#include <cuda_runtime.h>
#include <cuda_bf16.h>
#include <cstdint>

// ----------------------------------------------------------------------------
// DPO loss on GB300 (sm_103 base target — legacy bf16 HMMA, rt=8 floor).
// Round 9: R6 mainloop, CTA tile widened to 256x128 (16 warps, 4x4, warp tile
// 64x32 unchanged) -> 25% less L2 operand traffic. 1 CTA/SM, 144KB smem.
// ----------------------------------------------------------------------------

#define BM 256
#define BN 128
#define KC 64                 // K elems per stage: 128B rows (SW128 swizzle)
#define NSTAGE 3
#define THREADS 512

static constexpr int Hdim   = 4096;
static constexpr int Mtot   = 4096;          // 8*512 tokens
static constexpr int Vdim   = 32000;
static constexpr int NT_PER = Vdim / BN;     // 250 N-tiles per matrix
static constexpr int NT_TOT = 2 * NT_PER;    // 500
static constexpr int NKT    = Hdim / KC;     // 64 k-chunks

static constexpr int A_BYTES  = BM * 128;    // 32 KB
static constexpr int B_BYTES  = BN * 128;    // 16 KB
static constexpr int STAGE_B  = A_BYTES + B_BYTES;          // 48 KB
static constexpr int DSMEM    = 1024 + NSTAGE * STAGE_B;    // ~145 KB

// ---------------- scratch (allocation-free __device__ globals) ----------------
__device__ __nv_bfloat16 g_xbf[(size_t)Mtot * Hdim];   //  33.5 MB
__device__ __nv_bfloat16 g_wbf[(size_t)Vdim * Hdim];   // 262 MB
__device__ __nv_bfloat16 g_rbf[(size_t)Vdim * Hdim];   // 262 MB
__device__ float g_pmax[NT_TOT * Mtot];
__device__ float g_psum[NT_TOT * Mtot];
__device__ float g_tokW[Mtot];
__device__ float g_tokR[Mtot];
__device__ float g_lzW[Mtot];
__device__ float g_lzR[Mtot];
__device__ int   g_y_is64;

__device__ __forceinline__ uint32_t smem_u32(const void* p) {
    return (uint32_t)__cvta_generic_to_shared(p);
}
__device__ __forceinline__ void cp_async16(uint32_t dst, const void* src) {
    asm volatile("cp.async.cg.shared.global [%0], [%1], 16;\n" :: "r"(dst), "l"(src));
}
#define SWZ(x) ((x) ^ (((x) >> 3) & 0x70))

// label accessor, safe under int32 or int64 storage
__device__ __forceinline__ int get_label(const void* y, int m) {
    if (g_y_is64) return (int)((const long long*)y)[m];
    return ((const int*)y)[m];
}

// ----------------------------------------------------------------------------
__global__ void detect_y_kernel(const int* __restrict__ y32)
{
    if (threadIdx.x == 0) {
        int is64 = 1;
        for (int i = 0; i < 64; i++) {
            int hi = y32[2 * i + 1];
            if (hi != 0 && hi != -1) { is64 = 0; break; }
        }
        g_y_is64 = is64;
    }
}

// ----------------------------------------------------------------------------
// Single merged fp32 -> bf16 convert over x, W, ref_W (one launch).
// ----------------------------------------------------------------------------
static constexpr size_t N8_X = (size_t)Mtot * Hdim / 8;
static constexpr size_t N8_W = (size_t)Vdim * Hdim / 8;
static constexpr size_t N8_TOT = N8_X + 2 * N8_W;

__global__ __launch_bounds__(256) void convert_all_kernel(
    const float* __restrict__ x, const float* __restrict__ W,
    const float* __restrict__ R)
{
    size_t i = (size_t)blockIdx.x * blockDim.x + threadIdx.x;
    const size_t stride = (size_t)gridDim.x * blockDim.x;
    for (; i < N8_TOT; i += stride) {
        const float* src;
        __nv_bfloat16* dst;
        size_t j;
        if (i < N8_X)               { src = x; dst = g_xbf; j = i; }
        else if (i < N8_X + N8_W)   { src = W; dst = g_wbf; j = i - N8_X; }
        else                        { src = R; dst = g_rbf; j = i - N8_X - N8_W; }
        const float4* s = reinterpret_cast<const float4*>(src) + 2 * j;
        float4 a = s[0], b = s[1];
        __nv_bfloat162 o[4] = {
            __floats2bfloat162_rn(a.x, a.y), __floats2bfloat162_rn(a.z, a.w),
            __floats2bfloat162_rn(b.x, b.y), __floats2bfloat162_rn(b.z, b.w)};
        *reinterpret_cast<uint4*>(dst + j * 8) = *reinterpret_cast<const uint4*>(o);
    }
}

// ----------------------------------------------------------------------------
// Main GEMM + online LSE epilogue. grid=(16 mt [fast], 500 nt), block=512.
// 16 warps in a 4x4 (M x N) grid; each warp computes 64x32 (same as R6).
// ----------------------------------------------------------------------------
__global__ __launch_bounds__(THREADS, 1) void lse_kernel()
{
    extern __shared__ char dsm[];
    const uint32_t raw  = smem_u32(dsm);
    const uint32_t stg  = (raw + 1023) & ~1023u;   // 1024-aligned

    __shared__ float s_red[BM * 4];
    __shared__ float s_rowmax[BM];

    const int tid  = threadIdx.x;
    const int warp = tid >> 5, lane = tid & 31;
    const int wm   = warp >> 2, wn = warp & 3;     // 4 x 4 warp grid

    const int mt = blockIdx.x, nt = blockIdx.y;
    const int m0 = mt * BM;
    const int n0 = (nt < NT_PER ? nt : nt - NT_PER) * BN;
    const __nv_bfloat16* asrc = g_xbf + (size_t)m0 * Hdim;
    const __nv_bfloat16* bsrc = ((nt < NT_PER) ? g_wbf : g_rbf) + (size_t)n0 * Hdim;

    float acc[4][4][4];
#pragma unroll
    for (int i = 0; i < 4; i++)
#pragma unroll
        for (int j = 0; j < 4; j++)
#pragma unroll
            for (int c = 0; c < 4; c++) acc[i][j][c] = 0.f;

    auto load_stage = [&](int slot, int kt) {
        const uint32_t a_base = stg + slot * STAGE_B;
        const uint32_t b_base = a_base + A_BYTES;
        const int k0 = kt * KC;
        // A: 256 rows x 8 chunks = 2048 ids over 512 threads
#pragma unroll
        for (int i = 0; i < 4; i++) {
            int id  = tid + i * THREADS;
            int row = id >> 3, c = id & 7;
            cp_async16(a_base + SWZ(row * 128 + c * 16),
                       asrc + (size_t)row * Hdim + k0 + c * 8);
        }
        // B: 128 rows x 8 chunks = 1024 ids
#pragma unroll
        for (int i = 0; i < 2; i++) {
            int id  = tid + i * THREADS;
            int row = id >> 3, c = id & 7;
            cp_async16(b_base + SWZ(row * 128 + c * 16),
                       bsrc + (size_t)row * Hdim + k0 + c * 8);
        }
        asm volatile("cp.async.commit_group;" ::: "memory");
    };

    auto compute = [&](int slot) {
        const uint32_t a_base = stg + slot * STAGE_B;
        const uint32_t b_base = a_base + A_BYTES;
#pragma unroll
        for (int ks = 0; ks < 4; ks++) {       // 4 x K=16 inside the 64 chunk
            uint32_t af[4][4], bf[4][2];
            const int arow = wm * 64 + (lane & 15);
            const int asel = (lane >> 4) & 1;
#pragma unroll
            for (int mi = 0; mi < 4; mi++) {
                uint32_t addr = a_base +
                    SWZ((uint32_t)(arow + mi * 16) * 128 + ks * 32 + asel * 16);
                asm volatile("ldmatrix.sync.aligned.m8n8.x4.shared.b16 {%0,%1,%2,%3}, [%4];"
                             : "=r"(af[mi][0]), "=r"(af[mi][1]),
                               "=r"(af[mi][2]), "=r"(af[mi][3])
                             : "r"(addr));
            }
            // B: x4 over pairs of 8-col groups.
#pragma unroll
            for (int np = 0; np < 2; np++) {
                const uint32_t brow = wn * 32 + np * 16 +
                                      ((lane >> 4) << 3) + (lane & 7);
                const uint32_t bsel = (lane >> 3) & 1;
                uint32_t addr = b_base + SWZ(brow * 128 + ks * 32 + bsel * 16);
                asm volatile("ldmatrix.sync.aligned.m8n8.x4.shared.b16 {%0,%1,%2,%3}, [%4];"
                             : "=r"(bf[2 * np][0]), "=r"(bf[2 * np][1]),
                               "=r"(bf[2 * np + 1][0]), "=r"(bf[2 * np + 1][1])
                             : "r"(addr));
            }
#pragma unroll
            for (int mi = 0; mi < 4; mi++)
#pragma unroll
                for (int ni = 0; ni < 4; ni++)
                    asm volatile(
                        "mma.sync.aligned.m16n8k16.row.col.f32.bf16.bf16.f32 "
                        "{%0,%1,%2,%3}, {%4,%5,%6,%7}, {%8,%9}, {%0,%1,%2,%3};"
                        : "+f"(acc[mi][ni][0]), "+f"(acc[mi][ni][1]),
                          "+f"(acc[mi][ni][2]), "+f"(acc[mi][ni][3])
                        : "r"(af[mi][0]), "r"(af[mi][1]), "r"(af[mi][2]), "r"(af[mi][3]),
                          "r"(bf[ni][0]), "r"(bf[ni][1]));
        }
    };

    // prologue: fill NSTAGE-1 stages
    load_stage(0, 0);
    load_stage(1, 1);

    for (int kt = 0; kt < NKT; kt++) {
        const int slot = kt % NSTAGE;
        if (kt + 2 < NKT) {
            asm volatile("cp.async.wait_group 1;" ::: "memory");
        } else {
            asm volatile("cp.async.wait_group 0;" ::: "memory");
        }
        __syncthreads();
        if (kt + 2 < NKT) load_stage((kt + 2) % NSTAGE, kt + 2);
        compute(slot);
    }

    // ---- fused epilogue: per-token max / sumexp over this 128-col tile ----
    const float NEG = -1e30f;
#pragma unroll
    for (int mi = 0; mi < 4; mi++) {
        float mlo = NEG, mhi = NEG;
#pragma unroll
        for (int ni = 0; ni < 4; ni++) {
            mlo = fmaxf(mlo, fmaxf(acc[mi][ni][0], acc[mi][ni][1]));
            mhi = fmaxf(mhi, fmaxf(acc[mi][ni][2], acc[mi][ni][3]));
        }
#pragma unroll
        for (int o = 1; o < 4; o <<= 1) {
            mlo = fmaxf(mlo, __shfl_xor_sync(0xffffffffu, mlo, o));
            mhi = fmaxf(mhi, __shfl_xor_sync(0xffffffffu, mhi, o));
        }
        if ((lane & 3) == 0) {
            int rlo = wm * 64 + mi * 16 + (lane >> 2);
            s_red[rlo * 4 + wn]       = mlo;
            s_red[(rlo + 8) * 4 + wn] = mhi;
        }
    }
    __syncthreads();
    if (tid < BM) {
        s_rowmax[tid] = fmaxf(fmaxf(s_red[tid * 4 + 0], s_red[tid * 4 + 1]),
                              fmaxf(s_red[tid * 4 + 2], s_red[tid * 4 + 3]));
    }
    __syncthreads();
#pragma unroll
    for (int mi = 0; mi < 4; mi++) {
        int rlo = wm * 64 + mi * 16 + (lane >> 2);
        int rhi = rlo + 8;
        float Mlo = s_rowmax[rlo], Mhi = s_rowmax[rhi];
        float slo = 0.f, shi = 0.f;
#pragma unroll
        for (int ni = 0; ni < 4; ni++) {
            slo += __expf(acc[mi][ni][0] - Mlo) + __expf(acc[mi][ni][1] - Mlo);
            shi += __expf(acc[mi][ni][2] - Mhi) + __expf(acc[mi][ni][3] - Mhi);
        }
#pragma unroll
        for (int o = 1; o < 4; o <<= 1) {
            slo += __shfl_xor_sync(0xffffffffu, slo, o);
            shi += __shfl_xor_sync(0xffffffffu, shi, o);
        }
        if ((lane & 3) == 0) {
            s_red[rlo * 4 + wn] = slo;
            s_red[rhi * 4 + wn] = shi;
        }
    }
    __syncthreads();
    if (tid < BM) {
        float s = s_red[tid * 4 + 0] + s_red[tid * 4 + 1] +
                  s_red[tid * 4 + 2] + s_red[tid * 4 + 3];
        g_pmax[(size_t)nt * Mtot + m0 + tid] = s_rowmax[tid];
        g_psum[(size_t)nt * Mtot + m0 + tid] = s;
    }
}

// ----------------------------------------------------------------------------
// Combine per-tile partials -> logZ per token, per matrix. grid=4096, block=256
// ----------------------------------------------------------------------------
__global__ void reduce_lz_kernel()
{
    __shared__ float sm[256];
    __shared__ float ss[256];
    const int m = blockIdx.x, tid = threadIdx.x;
#pragma unroll
    for (int mat = 0; mat < 2; mat++) {
        const int base = mat * NT_PER;
        float mx = -1e30f, sv = 0.f;
        if (tid < NT_PER) {
            mx = g_pmax[(size_t)(base + tid) * Mtot + m];
            sv = g_psum[(size_t)(base + tid) * Mtot + m];
        }
        sm[tid] = mx; __syncthreads();
        for (int s = 128; s > 0; s >>= 1) {
            if (tid < s) sm[tid] = fmaxf(sm[tid], sm[tid + s]);
            __syncthreads();
        }
        const float M = sm[0];
        ss[tid] = (tid < NT_PER) ? sv * expf(mx - M) : 0.f;
        __syncthreads();
        for (int s = 128; s > 0; s >>= 1) {
            if (tid < s) ss[tid] += ss[tid + s];
            __syncthreads();
        }
        if (tid == 0) {
            float lz = M + logf(ss[0]);
            if (mat == 0) g_lzW[m] = lz; else g_lzR[m] = lz;
        }
        __syncthreads();
    }
}

// ----------------------------------------------------------------------------
// Exact fp32 token logits: one warp per token. grid=1024, block=128
// ----------------------------------------------------------------------------
__global__ void tok_kernel(const float* __restrict__ x,
                           const float* __restrict__ W,
                           const float* __restrict__ refW,
                           const void* __restrict__ y)
{
    const int warp = threadIdx.x >> 5, lane = threadIdx.x & 31;
    const int m = blockIdx.x * 4 + warp;
    int idx = get_label(y, m);
    if (idx < 0 || idx >= Vdim) idx = 0;     // defensive clamp
    const float4* xr = reinterpret_cast<const float4*>(x    + (size_t)m   * Hdim);
    const float4* wr = reinterpret_cast<const float4*>(W    + (size_t)idx * Hdim);
    const float4* rr = reinterpret_cast<const float4*>(refW + (size_t)idx * Hdim);
    float sw = 0.f, sr = 0.f;
    for (int j = lane; j < Hdim / 4; j += 32) {
        float4 a = xr[j], b = wr[j], c = rr[j];
        sw += a.x * b.x + a.y * b.y + a.z * b.z + a.w * b.w;
        sr += a.x * c.x + a.y * c.y + a.z * c.z + a.w * c.w;
    }
#pragma unroll
    for (int o = 16; o > 0; o >>= 1) {
        sw += __shfl_xor_sync(0xffffffffu, sw, o);
        sr += __shfl_xor_sync(0xffffffffu, sr, o);
    }
    if (lane == 0) { g_tokW[m] = sw; g_tokR[m] = sr; }
}

// ----------------------------------------------------------------------------
// Final DPO scalar. one block of 512
// ----------------------------------------------------------------------------
__global__ void final_kernel(const void* __restrict__ y, float* __restrict__ out)
{
    __shared__ float red[512];
    __shared__ float pav[8], rav[8];
    const int tid = threadIdx.x;
    for (int b = 0; b < 8; b++) {
        const int m = b * 512 + tid;
        const int yv = get_label(y, m);
        const bool v = (yv != -100);
        const float p = v ? (g_tokW[m] - g_lzW[m]) : 0.f;
        const float r = v ? (g_tokR[m] - g_lzR[m]) : 0.f;
        const float c = v ? 1.f : 0.f;

        red[tid] = p; __syncthreads();
        for (int s = 256; s > 0; s >>= 1) { if (tid < s) red[tid] += red[tid + s]; __syncthreads(); }
        float ps = red[0]; __syncthreads();

        red[tid] = r; __syncthreads();
        for (int s = 256; s > 0; s >>= 1) { if (tid < s) red[tid] += red[tid + s]; __syncthreads(); }
        float rs = red[0]; __syncthreads();

        red[tid] = c; __syncthreads();
        for (int s = 256; s > 0; s >>= 1) { if (tid < s) red[tid] += red[tid + s]; __syncthreads(); }
        float cs = red[0]; __syncthreads();

        if (tid == 0) { pav[b] = ps / cs; rav[b] = rs / cs; }
        __syncthreads();
    }
    if (tid == 0) {
        float loss = 0.f;
#pragma unroll
        for (int i = 0; i < 4; i++) {
            float z = 0.1f * ((pav[i] - rav[i]) - (pav[i + 4] - rav[i + 4]));
            loss += log1pf(expf(-z));
        }
        out[0] = loss * 0.25f;
    }
}

// ----------------------------------------------------------------------------
extern "C" void kernel_launch(void* const* d_in, const int* in_sizes, int n_in,
                              void* d_out, int out_size)
{
    const float* x = nullptr;
    const void*  y = nullptr;
    const float* Wm[2] = {nullptr, nullptr};
    int wcount = 0;
    for (int i = 0; i < n_in; i++) {
        if (in_sizes[i] == 16777216)                          x = (const float*)d_in[i];
        else if (in_sizes[i] == 4096 || in_sizes[i] == 8192)  y = d_in[i];
        else if (wcount < 2)                                  Wm[wcount++] = (const float*)d_in[i];
    }
    if (!x)      x     = (const float*)d_in[0];
    if (!y)      y     = d_in[1];
    if (!Wm[0])  Wm[0] = (const float*)d_in[2];
    if (!Wm[1])  Wm[1] = (const float*)d_in[3];
    const float* W    = Wm[0];
    const float* refW = Wm[1];

    cudaFuncSetAttribute(lse_kernel, cudaFuncAttributeMaxDynamicSharedMemorySize, DSMEM);

    detect_y_kernel<<<1, 32>>>((const int*)y);
    convert_all_kernel<<<4096, 256>>>(x, W, refW);

    dim3 grid(Mtot / BM, NT_TOT);   // (16 [fast: x L2-resident], 500)
    lse_kernel<<<grid, THREADS, DSMEM>>>();

    reduce_lz_kernel<<<Mtot, 256>>>();
    tok_kernel<<<Mtot / 4, 128>>>(x, W, refW, y);
    final_kernel<<<1, 512>>>(y, (float*)d_out);
}

// round 11
// speedup vs baseline: 1.1208x; 1.1208x over previous
#include <cuda_runtime.h>
#include <cuda_bf16.h>
#include <cstdint>

// ----------------------------------------------------------------------------
// DPO loss on GB300 (sm_103 base target — legacy bf16 HMMA, rt=8).
// Round 10 (resubmit after infra failure): warp tile 64x64 (4 warps, 2x2,
// 128 threads, CTA 128x128, 2 CTA/SM) -> smem read traffic per kt drops
// 96KB->64KB; HMMA becomes cleanly binding. Plus: tok fused into convert.
// ----------------------------------------------------------------------------

#define BM 128
#define BN 128
#define KC 64                 // K elems per stage: 128B rows (SW128 swizzle)
#define NSTAGE 3
#define THREADS 128

static constexpr int Hdim   = 4096;
static constexpr int Mtot   = 4096;          // 8*512 tokens
static constexpr int Vdim   = 32000;
static constexpr int NT_PER = Vdim / BN;     // 250 N-tiles per matrix
static constexpr int NT_TOT = 2 * NT_PER;    // 500
static constexpr int NKT    = Hdim / KC;     // 64 k-chunks

static constexpr int A_BYTES  = BM * 128;    // 16 KB
static constexpr int B_BYTES  = BN * 128;    // 16 KB
static constexpr int STAGE_B  = A_BYTES + B_BYTES;          // 32 KB
static constexpr int DSMEM    = 1024 + NSTAGE * STAGE_B;    // ~97 KB

// ---------------- scratch (allocation-free __device__ globals) ----------------
__device__ __nv_bfloat16 g_xbf[(size_t)Mtot * Hdim];   //  33.5 MB
__device__ __nv_bfloat16 g_wbf[(size_t)Vdim * Hdim];   // 262 MB
__device__ __nv_bfloat16 g_rbf[(size_t)Vdim * Hdim];   // 262 MB
__device__ float g_pmax[NT_TOT * Mtot];
__device__ float g_psum[NT_TOT * Mtot];
__device__ float g_tokW[Mtot];
__device__ float g_tokR[Mtot];
__device__ float g_lzW[Mtot];
__device__ float g_lzR[Mtot];
__device__ int   g_y_is64;

__device__ __forceinline__ uint32_t smem_u32(const void* p) {
    return (uint32_t)__cvta_generic_to_shared(p);
}
__device__ __forceinline__ void cp_async16(uint32_t dst, const void* src) {
    asm volatile("cp.async.cg.shared.global [%0], [%1], 16;\n" :: "r"(dst), "l"(src));
}
#define SWZ(x) ((x) ^ (((x) >> 3) & 0x70))

// label accessor, safe under int32 or int64 storage
__device__ __forceinline__ int get_label(const void* y, int m) {
    if (g_y_is64) return (int)((const long long*)y)[m];
    return ((const int*)y)[m];
}

// ----------------------------------------------------------------------------
__global__ void detect_y_kernel(const int* __restrict__ y32)
{
    if (threadIdx.x == 0) {
        int is64 = 1;
        for (int i = 0; i < 64; i++) {
            int hi = y32[2 * i + 1];
            if (hi != 0 && hi != -1) { is64 = 0; break; }
        }
        g_y_is64 = is64;
    }
}

// ----------------------------------------------------------------------------
// Fused: fp32 -> bf16 convert (blocks 0..4095) + exact token logits (blocks
// 4096..4607; 8 warps x 1 token each = 4096 tokens).
// ----------------------------------------------------------------------------
static constexpr size_t N8_X = (size_t)Mtot * Hdim / 8;
static constexpr size_t N8_W = (size_t)Vdim * Hdim / 8;
static constexpr size_t N8_TOT = N8_X + 2 * N8_W;
static constexpr int CONV_BLOCKS = 4096;
static constexpr int TOK_BLOCKS  = Mtot / 8;   // 512

__global__ __launch_bounds__(256) void convert_tok_kernel(
    const float* __restrict__ x, const float* __restrict__ W,
    const float* __restrict__ R, const void* __restrict__ y)
{
    if (blockIdx.x < CONV_BLOCKS) {
        size_t i = (size_t)blockIdx.x * blockDim.x + threadIdx.x;
        const size_t stride = (size_t)CONV_BLOCKS * blockDim.x;
        for (; i < N8_TOT; i += stride) {
            const float* src;
            __nv_bfloat16* dst;
            size_t j;
            if (i < N8_X)               { src = x; dst = g_xbf; j = i; }
            else if (i < N8_X + N8_W)   { src = W; dst = g_wbf; j = i - N8_X; }
            else                        { src = R; dst = g_rbf; j = i - N8_X - N8_W; }
            const float4* s = reinterpret_cast<const float4*>(src) + 2 * j;
            float4 a = s[0], b = s[1];
            __nv_bfloat162 o[4] = {
                __floats2bfloat162_rn(a.x, a.y), __floats2bfloat162_rn(a.z, a.w),
                __floats2bfloat162_rn(b.x, b.y), __floats2bfloat162_rn(b.z, b.w)};
            *reinterpret_cast<uint4*>(dst + j * 8) = *reinterpret_cast<const uint4*>(o);
        }
    } else {
        // token-logit blocks: one warp per token, fp32 exact
        const int blk  = blockIdx.x - CONV_BLOCKS;      // 0..511
        const int warp = threadIdx.x >> 5, lane = threadIdx.x & 31;
        const int m = blk * 8 + warp;
        int idx = get_label(y, m);
        if (idx < 0 || idx >= Vdim) idx = 0;            // defensive clamp
        const float4* xr = reinterpret_cast<const float4*>(x + (size_t)m   * Hdim);
        const float4* wr = reinterpret_cast<const float4*>(W + (size_t)idx * Hdim);
        const float4* rr = reinterpret_cast<const float4*>(R + (size_t)idx * Hdim);
        float sw = 0.f, sr = 0.f;
        for (int j = lane; j < Hdim / 4; j += 32) {
            float4 a = xr[j], b = wr[j], c = rr[j];
            sw += a.x * b.x + a.y * b.y + a.z * b.z + a.w * b.w;
            sr += a.x * c.x + a.y * c.y + a.z * c.z + a.w * c.w;
        }
#pragma unroll
        for (int o = 16; o > 0; o >>= 1) {
            sw += __shfl_xor_sync(0xffffffffu, sw, o);
            sr += __shfl_xor_sync(0xffffffffu, sr, o);
        }
        if (lane == 0) { g_tokW[m] = sw; g_tokR[m] = sr; }
    }
}

// ----------------------------------------------------------------------------
// Main GEMM + online LSE epilogue. grid=(32 mt [fast], 500 nt), block=128.
// 4 warps in a 2x2 (M x N) grid; each warp computes 64x64.
// ----------------------------------------------------------------------------
__global__ __launch_bounds__(THREADS, 2) void lse_kernel()
{
    extern __shared__ char dsm[];
    const uint32_t raw  = smem_u32(dsm);
    const uint32_t stg  = (raw + 1023) & ~1023u;   // 1024-aligned

    __shared__ float s_red[BM * 2];
    __shared__ float s_rowmax[BM];

    const int tid  = threadIdx.x;
    const int warp = tid >> 5, lane = tid & 31;
    const int wm   = warp >> 1, wn = warp & 1;     // 2 x 2 warp grid

    const int mt = blockIdx.x, nt = blockIdx.y;
    const int m0 = mt * BM;
    const int n0 = (nt < NT_PER ? nt : nt - NT_PER) * BN;
    const __nv_bfloat16* asrc = g_xbf + (size_t)m0 * Hdim;
    const __nv_bfloat16* bsrc = ((nt < NT_PER) ? g_wbf : g_rbf) + (size_t)n0 * Hdim;

    float acc[4][8][4];            // 128 fp32 accumulators / thread
#pragma unroll
    for (int i = 0; i < 4; i++)
#pragma unroll
        for (int j = 0; j < 8; j++)
#pragma unroll
            for (int c = 0; c < 4; c++) acc[i][j][c] = 0.f;

    auto load_stage = [&](int slot, int kt) {
        const uint32_t a_base = stg + slot * STAGE_B;
        const uint32_t b_base = a_base + A_BYTES;
        const int k0 = kt * KC;
#pragma unroll
        for (int i = 0; i < 8; i++) {
            int id  = tid + i * THREADS;      // 0..1023
            int row = id >> 3, c = id & 7;    // 128 rows x 8 chunks
            cp_async16(a_base + SWZ(row * 128 + c * 16),
                       asrc + (size_t)row * Hdim + k0 + c * 8);
            cp_async16(b_base + SWZ(row * 128 + c * 16),
                       bsrc + (size_t)row * Hdim + k0 + c * 8);
        }
        asm volatile("cp.async.commit_group;" ::: "memory");
    };

    auto compute = [&](int slot) {
        const uint32_t a_base = stg + slot * STAGE_B;
        const uint32_t b_base = a_base + A_BYTES;
#pragma unroll
        for (int ks = 0; ks < 4; ks++) {       // 4 x K=16 inside the 64 chunk
            uint32_t af[4][4], bf[8][2];
            const int arow = wm * 64 + (lane & 15);
            const int asel = (lane >> 4) & 1;
#pragma unroll
            for (int mi = 0; mi < 4; mi++) {
                uint32_t addr = a_base +
                    SWZ((uint32_t)(arow + mi * 16) * 128 + ks * 32 + asel * 16);
                asm volatile("ldmatrix.sync.aligned.m8n8.x4.shared.b16 {%0,%1,%2,%3}, [%4];"
                             : "=r"(af[mi][0]), "=r"(af[mi][1]),
                               "=r"(af[mi][2]), "=r"(af[mi][3])
                             : "r"(addr));
            }
            // B: x4 over pairs of 8-col groups (proven R6 mapping).
#pragma unroll
            for (int np = 0; np < 4; np++) {
                const uint32_t brow = wn * 64 + np * 16 +
                                      ((lane >> 4) << 3) + (lane & 7);
                const uint32_t bsel = (lane >> 3) & 1;
                uint32_t addr = b_base + SWZ(brow * 128 + ks * 32 + bsel * 16);
                asm volatile("ldmatrix.sync.aligned.m8n8.x4.shared.b16 {%0,%1,%2,%3}, [%4];"
                             : "=r"(bf[2 * np][0]), "=r"(bf[2 * np][1]),
                               "=r"(bf[2 * np + 1][0]), "=r"(bf[2 * np + 1][1])
                             : "r"(addr));
            }
#pragma unroll
            for (int mi = 0; mi < 4; mi++)
#pragma unroll
                for (int ni = 0; ni < 8; ni++)
                    asm volatile(
                        "mma.sync.aligned.m16n8k16.row.col.f32.bf16.bf16.f32 "
                        "{%0,%1,%2,%3}, {%4,%5,%6,%7}, {%8,%9}, {%0,%1,%2,%3};"
                        : "+f"(acc[mi][ni][0]), "+f"(acc[mi][ni][1]),
                          "+f"(acc[mi][ni][2]), "+f"(acc[mi][ni][3])
                        : "r"(af[mi][0]), "r"(af[mi][1]), "r"(af[mi][2]), "r"(af[mi][3]),
                          "r"(bf[ni][0]), "r"(bf[ni][1]));
        }
    };

    // prologue: fill NSTAGE-1 stages
    load_stage(0, 0);
    load_stage(1, 1);

    for (int kt = 0; kt < NKT; kt++) {
        const int slot = kt % NSTAGE;
        if (kt + 2 < NKT) {
            asm volatile("cp.async.wait_group 1;" ::: "memory");
        } else {
            asm volatile("cp.async.wait_group 0;" ::: "memory");
        }
        __syncthreads();
        if (kt + 2 < NKT) load_stage((kt + 2) % NSTAGE, kt + 2);
        compute(slot);
    }

    // ---- fused epilogue: per-token max / sumexp over this 128-col tile ----
    const float NEG = -1e30f;
#pragma unroll
    for (int mi = 0; mi < 4; mi++) {
        float mlo = NEG, mhi = NEG;
#pragma unroll
        for (int ni = 0; ni < 8; ni++) {
            mlo = fmaxf(mlo, fmaxf(acc[mi][ni][0], acc[mi][ni][1]));
            mhi = fmaxf(mhi, fmaxf(acc[mi][ni][2], acc[mi][ni][3]));
        }
#pragma unroll
        for (int o = 1; o < 4; o <<= 1) {
            mlo = fmaxf(mlo, __shfl_xor_sync(0xffffffffu, mlo, o));
            mhi = fmaxf(mhi, __shfl_xor_sync(0xffffffffu, mhi, o));
        }
        if ((lane & 3) == 0) {
            int rlo = wm * 64 + mi * 16 + (lane >> 2);
            s_red[rlo * 2 + wn]       = mlo;
            s_red[(rlo + 8) * 2 + wn] = mhi;
        }
    }
    __syncthreads();
    if (tid < BM) {
        s_rowmax[tid] = fmaxf(s_red[tid * 2 + 0], s_red[tid * 2 + 1]);
    }
    __syncthreads();
#pragma unroll
    for (int mi = 0; mi < 4; mi++) {
        int rlo = wm * 64 + mi * 16 + (lane >> 2);
        int rhi = rlo + 8;
        float Mlo = s_rowmax[rlo], Mhi = s_rowmax[rhi];
        float slo = 0.f, shi = 0.f;
#pragma unroll
        for (int ni = 0; ni < 8; ni++) {
            slo += __expf(acc[mi][ni][0] - Mlo) + __expf(acc[mi][ni][1] - Mlo);
            shi += __expf(acc[mi][ni][2] - Mhi) + __expf(acc[mi][ni][3] - Mhi);
        }
#pragma unroll
        for (int o = 1; o < 4; o <<= 1) {
            slo += __shfl_xor_sync(0xffffffffu, slo, o);
            shi += __shfl_xor_sync(0xffffffffu, shi, o);
        }
        if ((lane & 3) == 0) {
            s_red[rlo * 2 + wn] = slo;
            s_red[rhi * 2 + wn] = shi;
        }
    }
    __syncthreads();
    if (tid < BM) {
        float s = s_red[tid * 2 + 0] + s_red[tid * 2 + 1];
        g_pmax[(size_t)nt * Mtot + m0 + tid] = s_rowmax[tid];
        g_psum[(size_t)nt * Mtot + m0 + tid] = s;
    }
}

// ----------------------------------------------------------------------------
// Combine per-tile partials -> logZ per token, per matrix. grid=4096, block=256
// ----------------------------------------------------------------------------
__global__ void reduce_lz_kernel()
{
    __shared__ float sm[256];
    __shared__ float ss[256];
    const int m = blockIdx.x, tid = threadIdx.x;
#pragma unroll
    for (int mat = 0; mat < 2; mat++) {
        const int base = mat * NT_PER;
        float mx = -1e30f, sv = 0.f;
        if (tid < NT_PER) {
            mx = g_pmax[(size_t)(base + tid) * Mtot + m];
            sv = g_psum[(size_t)(base + tid) * Mtot + m];
        }
        sm[tid] = mx; __syncthreads();
        for (int s = 128; s > 0; s >>= 1) {
            if (tid < s) sm[tid] = fmaxf(sm[tid], sm[tid + s]);
            __syncthreads();
        }
        const float M = sm[0];
        ss[tid] = (tid < NT_PER) ? sv * expf(mx - M) : 0.f;
        __syncthreads();
        for (int s = 128; s > 0; s >>= 1) {
            if (tid < s) ss[tid] += ss[tid + s];
            __syncthreads();
        }
        if (tid == 0) {
            float lz = M + logf(ss[0]);
            if (mat == 0) g_lzW[m] = lz; else g_lzR[m] = lz;
        }
        __syncthreads();
    }
}

// ----------------------------------------------------------------------------
// Final DPO scalar. one block of 512
// ----------------------------------------------------------------------------
__global__ void final_kernel(const void* __restrict__ y, float* __restrict__ out)
{
    __shared__ float red[512];
    __shared__ float pav[8], rav[8];
    const int tid = threadIdx.x;
    for (int b = 0; b < 8; b++) {
        const int m = b * 512 + tid;
        const int yv = get_label(y, m);
        const bool v = (yv != -100);
        const float p = v ? (g_tokW[m] - g_lzW[m]) : 0.f;
        const float r = v ? (g_tokR[m] - g_lzR[m]) : 0.f;
        const float c = v ? 1.f : 0.f;

        red[tid] = p; __syncthreads();
        for (int s = 256; s > 0; s >>= 1) { if (tid < s) red[tid] += red[tid + s]; __syncthreads(); }
        float ps = red[0]; __syncthreads();

        red[tid] = r; __syncthreads();
        for (int s = 256; s > 0; s >>= 1) { if (tid < s) red[tid] += red[tid + s]; __syncthreads(); }
        float rs = red[0]; __syncthreads();

        red[tid] = c; __syncthreads();
        for (int s = 256; s > 0; s >>= 1) { if (tid < s) red[tid] += red[tid + s]; __syncthreads(); }
        float cs = red[0]; __syncthreads();

        if (tid == 0) { pav[b] = ps / cs; rav[b] = rs / cs; }
        __syncthreads();
    }
    if (tid == 0) {
        float loss = 0.f;
#pragma unroll
        for (int i = 0; i < 4; i++) {
            float z = 0.1f * ((pav[i] - rav[i]) - (pav[i + 4] - rav[i + 4]));
            loss += log1pf(expf(-z));
        }
        out[0] = loss * 0.25f;
    }
}

// ----------------------------------------------------------------------------
extern "C" void kernel_launch(void* const* d_in, const int* in_sizes, int n_in,
                              void* d_out, int out_size)
{
    const float* x = nullptr;
    const void*  y = nullptr;
    const float* Wm[2] = {nullptr, nullptr};
    int wcount = 0;
    for (int i = 0; i < n_in; i++) {
        if (in_sizes[i] == 16777216)                          x = (const float*)d_in[i];
        else if (in_sizes[i] == 4096 || in_sizes[i] == 8192)  y = d_in[i];
        else if (wcount < 2)                                  Wm[wcount++] = (const float*)d_in[i];
    }
    if (!x)      x     = (const float*)d_in[0];
    if (!y)      y     = d_in[1];
    if (!Wm[0])  Wm[0] = (const float*)d_in[2];
    if (!Wm[1])  Wm[1] = (const float*)d_in[3];
    const float* W    = Wm[0];
    const float* refW = Wm[1];

    cudaFuncSetAttribute(lse_kernel, cudaFuncAttributeMaxDynamicSharedMemorySize, DSMEM);

    detect_y_kernel<<<1, 32>>>((const int*)y);
    convert_tok_kernel<<<CONV_BLOCKS + TOK_BLOCKS, 256>>>(x, W, refW, y);

    dim3 grid(Mtot / BM, NT_TOT);   // (32 [fast: x L2-resident], 500)
    lse_kernel<<<grid, THREADS, DSMEM>>>();

    reduce_lz_kernel<<<Mtot, 256>>>();
    final_kernel<<<1, 512>>>(y, (float*)d_out);
}

// round 12
// speedup vs baseline: 1.1248x; 1.0036x over previous
#include <cuda_runtime.h>
#include <cuda_bf16.h>
#include <cstdint>

// ----------------------------------------------------------------------------
// DPO loss on GB300 (sm_103 base target — legacy bf16 HMMA, rt=8 ceiling).
// Round 12: R11 winner + coalesced reduce_lz (1 block / 32 tokens, online LSE
// merge; kills the 32x read amplification). lse/convert unchanged.
// ----------------------------------------------------------------------------

#define BM 128
#define BN 128
#define KC 64                 // K elems per stage: 128B rows (SW128 swizzle)
#define NSTAGE 3
#define THREADS 128

static constexpr int Hdim   = 4096;
static constexpr int Mtot   = 4096;          // 8*512 tokens
static constexpr int Vdim   = 32000;
static constexpr int NT_PER = Vdim / BN;     // 250 N-tiles per matrix
static constexpr int NT_TOT = 2 * NT_PER;    // 500
static constexpr int NKT    = Hdim / KC;     // 64 k-chunks

static constexpr int A_BYTES  = BM * 128;    // 16 KB
static constexpr int B_BYTES  = BN * 128;    // 16 KB
static constexpr int STAGE_B  = A_BYTES + B_BYTES;          // 32 KB
static constexpr int DSMEM    = 1024 + NSTAGE * STAGE_B;    // ~97 KB

// ---------------- scratch (allocation-free __device__ globals) ----------------
__device__ __nv_bfloat16 g_xbf[(size_t)Mtot * Hdim];   //  33.5 MB
__device__ __nv_bfloat16 g_wbf[(size_t)Vdim * Hdim];   // 262 MB
__device__ __nv_bfloat16 g_rbf[(size_t)Vdim * Hdim];   // 262 MB
__device__ float g_pmax[NT_TOT * Mtot];
__device__ float g_psum[NT_TOT * Mtot];
__device__ float g_tokW[Mtot];
__device__ float g_tokR[Mtot];
__device__ float g_lzW[Mtot];
__device__ float g_lzR[Mtot];
__device__ int   g_y_is64;

__device__ __forceinline__ uint32_t smem_u32(const void* p) {
    return (uint32_t)__cvta_generic_to_shared(p);
}
__device__ __forceinline__ void cp_async16(uint32_t dst, const void* src) {
    asm volatile("cp.async.cg.shared.global [%0], [%1], 16;\n" :: "r"(dst), "l"(src));
}
#define SWZ(x) ((x) ^ (((x) >> 3) & 0x70))

// label accessor, safe under int32 or int64 storage
__device__ __forceinline__ int get_label(const void* y, int m) {
    if (g_y_is64) return (int)((const long long*)y)[m];
    return ((const int*)y)[m];
}

// ----------------------------------------------------------------------------
__global__ void detect_y_kernel(const int* __restrict__ y32)
{
    if (threadIdx.x == 0) {
        int is64 = 1;
        for (int i = 0; i < 64; i++) {
            int hi = y32[2 * i + 1];
            if (hi != 0 && hi != -1) { is64 = 0; break; }
        }
        g_y_is64 = is64;
    }
}

// ----------------------------------------------------------------------------
// Fused: fp32 -> bf16 convert (blocks 0..4095) + exact token logits (blocks
// 4096..4607; 8 warps x 1 token each = 4096 tokens).
// ----------------------------------------------------------------------------
static constexpr size_t N8_X = (size_t)Mtot * Hdim / 8;
static constexpr size_t N8_W = (size_t)Vdim * Hdim / 8;
static constexpr size_t N8_TOT = N8_X + 2 * N8_W;
static constexpr int CONV_BLOCKS = 4096;
static constexpr int TOK_BLOCKS  = Mtot / 8;   // 512

__global__ __launch_bounds__(256) void convert_tok_kernel(
    const float* __restrict__ x, const float* __restrict__ W,
    const float* __restrict__ R, const void* __restrict__ y)
{
    if (blockIdx.x < CONV_BLOCKS) {
        size_t i = (size_t)blockIdx.x * blockDim.x + threadIdx.x;
        const size_t stride = (size_t)CONV_BLOCKS * blockDim.x;
        for (; i < N8_TOT; i += stride) {
            const float* src;
            __nv_bfloat16* dst;
            size_t j;
            if (i < N8_X)               { src = x; dst = g_xbf; j = i; }
            else if (i < N8_X + N8_W)   { src = W; dst = g_wbf; j = i - N8_X; }
            else                        { src = R; dst = g_rbf; j = i - N8_X - N8_W; }
            const float4* s = reinterpret_cast<const float4*>(src) + 2 * j;
            float4 a = s[0], b = s[1];
            __nv_bfloat162 o[4] = {
                __floats2bfloat162_rn(a.x, a.y), __floats2bfloat162_rn(a.z, a.w),
                __floats2bfloat162_rn(b.x, b.y), __floats2bfloat162_rn(b.z, b.w)};
            *reinterpret_cast<uint4*>(dst + j * 8) = *reinterpret_cast<const uint4*>(o);
        }
    } else {
        // token-logit blocks: one warp per token, fp32 exact
        const int blk  = blockIdx.x - CONV_BLOCKS;      // 0..511
        const int warp = threadIdx.x >> 5, lane = threadIdx.x & 31;
        const int m = blk * 8 + warp;
        int idx = get_label(y, m);
        if (idx < 0 || idx >= Vdim) idx = 0;            // defensive clamp
        const float4* xr = reinterpret_cast<const float4*>(x + (size_t)m   * Hdim);
        const float4* wr = reinterpret_cast<const float4*>(W + (size_t)idx * Hdim);
        const float4* rr = reinterpret_cast<const float4*>(R + (size_t)idx * Hdim);
        float sw = 0.f, sr = 0.f;
        for (int j = lane; j < Hdim / 4; j += 32) {
            float4 a = xr[j], b = wr[j], c = rr[j];
            sw += a.x * b.x + a.y * b.y + a.z * b.z + a.w * b.w;
            sr += a.x * c.x + a.y * c.y + a.z * c.z + a.w * c.w;
        }
#pragma unroll
        for (int o = 16; o > 0; o >>= 1) {
            sw += __shfl_xor_sync(0xffffffffu, sw, o);
            sr += __shfl_xor_sync(0xffffffffu, sr, o);
        }
        if (lane == 0) { g_tokW[m] = sw; g_tokR[m] = sr; }
    }
}

// ----------------------------------------------------------------------------
// Main GEMM + online LSE epilogue. grid=(32 mt [fast], 500 nt), block=128.
// 4 warps in a 2x2 (M x N) grid; each warp computes 64x64. (R10/R11 winner)
// ----------------------------------------------------------------------------
__global__ __launch_bounds__(THREADS, 2) void lse_kernel()
{
    extern __shared__ char dsm[];
    const uint32_t raw  = smem_u32(dsm);
    const uint32_t stg  = (raw + 1023) & ~1023u;   // 1024-aligned

    __shared__ float s_red[BM * 2];
    __shared__ float s_rowmax[BM];

    const int tid  = threadIdx.x;
    const int warp = tid >> 5, lane = tid & 31;
    const int wm   = warp >> 1, wn = warp & 1;     // 2 x 2 warp grid

    const int mt = blockIdx.x, nt = blockIdx.y;
    const int m0 = mt * BM;
    const int n0 = (nt < NT_PER ? nt : nt - NT_PER) * BN;
    const __nv_bfloat16* asrc = g_xbf + (size_t)m0 * Hdim;
    const __nv_bfloat16* bsrc = ((nt < NT_PER) ? g_wbf : g_rbf) + (size_t)n0 * Hdim;

    float acc[4][8][4];            // 128 fp32 accumulators / thread
#pragma unroll
    for (int i = 0; i < 4; i++)
#pragma unroll
        for (int j = 0; j < 8; j++)
#pragma unroll
            for (int c = 0; c < 4; c++) acc[i][j][c] = 0.f;

    auto load_stage = [&](int slot, int kt) {
        const uint32_t a_base = stg + slot * STAGE_B;
        const uint32_t b_base = a_base + A_BYTES;
        const int k0 = kt * KC;
#pragma unroll
        for (int i = 0; i < 8; i++) {
            int id  = tid + i * THREADS;      // 0..1023
            int row = id >> 3, c = id & 7;    // 128 rows x 8 chunks
            cp_async16(a_base + SWZ(row * 128 + c * 16),
                       asrc + (size_t)row * Hdim + k0 + c * 8);
            cp_async16(b_base + SWZ(row * 128 + c * 16),
                       bsrc + (size_t)row * Hdim + k0 + c * 8);
        }
        asm volatile("cp.async.commit_group;" ::: "memory");
    };

    auto compute = [&](int slot) {
        const uint32_t a_base = stg + slot * STAGE_B;
        const uint32_t b_base = a_base + A_BYTES;
#pragma unroll
        for (int ks = 0; ks < 4; ks++) {       // 4 x K=16 inside the 64 chunk
            uint32_t af[4][4], bf[8][2];
            const int arow = wm * 64 + (lane & 15);
            const int asel = (lane >> 4) & 1;
#pragma unroll
            for (int mi = 0; mi < 4; mi++) {
                uint32_t addr = a_base +
                    SWZ((uint32_t)(arow + mi * 16) * 128 + ks * 32 + asel * 16);
                asm volatile("ldmatrix.sync.aligned.m8n8.x4.shared.b16 {%0,%1,%2,%3}, [%4];"
                             : "=r"(af[mi][0]), "=r"(af[mi][1]),
                               "=r"(af[mi][2]), "=r"(af[mi][3])
                             : "r"(addr));
            }
            // B: x4 over pairs of 8-col groups.
#pragma unroll
            for (int np = 0; np < 4; np++) {
                const uint32_t brow = wn * 64 + np * 16 +
                                      ((lane >> 4) << 3) + (lane & 7);
                const uint32_t bsel = (lane >> 3) & 1;
                uint32_t addr = b_base + SWZ(brow * 128 + ks * 32 + bsel * 16);
                asm volatile("ldmatrix.sync.aligned.m8n8.x4.shared.b16 {%0,%1,%2,%3}, [%4];"
                             : "=r"(bf[2 * np][0]), "=r"(bf[2 * np][1]),
                               "=r"(bf[2 * np + 1][0]), "=r"(bf[2 * np + 1][1])
                             : "r"(addr));
            }
#pragma unroll
            for (int mi = 0; mi < 4; mi++)
#pragma unroll
                for (int ni = 0; ni < 8; ni++)
                    asm volatile(
                        "mma.sync.aligned.m16n8k16.row.col.f32.bf16.bf16.f32 "
                        "{%0,%1,%2,%3}, {%4,%5,%6,%7}, {%8,%9}, {%0,%1,%2,%3};"
                        : "+f"(acc[mi][ni][0]), "+f"(acc[mi][ni][1]),
                          "+f"(acc[mi][ni][2]), "+f"(acc[mi][ni][3])
                        : "r"(af[mi][0]), "r"(af[mi][1]), "r"(af[mi][2]), "r"(af[mi][3]),
                          "r"(bf[ni][0]), "r"(bf[ni][1]));
        }
    };

    // prologue: fill NSTAGE-1 stages
    load_stage(0, 0);
    load_stage(1, 1);

    for (int kt = 0; kt < NKT; kt++) {
        const int slot = kt % NSTAGE;
        if (kt + 2 < NKT) {
            asm volatile("cp.async.wait_group 1;" ::: "memory");
        } else {
            asm volatile("cp.async.wait_group 0;" ::: "memory");
        }
        __syncthreads();
        if (kt + 2 < NKT) load_stage((kt + 2) % NSTAGE, kt + 2);
        compute(slot);
    }

    // ---- fused epilogue: per-token max / sumexp over this 128-col tile ----
    const float NEG = -1e30f;
#pragma unroll
    for (int mi = 0; mi < 4; mi++) {
        float mlo = NEG, mhi = NEG;
#pragma unroll
        for (int ni = 0; ni < 8; ni++) {
            mlo = fmaxf(mlo, fmaxf(acc[mi][ni][0], acc[mi][ni][1]));
            mhi = fmaxf(mhi, fmaxf(acc[mi][ni][2], acc[mi][ni][3]));
        }
#pragma unroll
        for (int o = 1; o < 4; o <<= 1) {
            mlo = fmaxf(mlo, __shfl_xor_sync(0xffffffffu, mlo, o));
            mhi = fmaxf(mhi, __shfl_xor_sync(0xffffffffu, mhi, o));
        }
        if ((lane & 3) == 0) {
            int rlo = wm * 64 + mi * 16 + (lane >> 2);
            s_red[rlo * 2 + wn]       = mlo;
            s_red[(rlo + 8) * 2 + wn] = mhi;
        }
    }
    __syncthreads();
    if (tid < BM) {
        s_rowmax[tid] = fmaxf(s_red[tid * 2 + 0], s_red[tid * 2 + 1]);
    }
    __syncthreads();
#pragma unroll
    for (int mi = 0; mi < 4; mi++) {
        int rlo = wm * 64 + mi * 16 + (lane >> 2);
        int rhi = rlo + 8;
        float Mlo = s_rowmax[rlo], Mhi = s_rowmax[rhi];
        float slo = 0.f, shi = 0.f;
#pragma unroll
        for (int ni = 0; ni < 8; ni++) {
            slo += __expf(acc[mi][ni][0] - Mlo) + __expf(acc[mi][ni][1] - Mlo);
            shi += __expf(acc[mi][ni][2] - Mhi) + __expf(acc[mi][ni][3] - Mhi);
        }
#pragma unroll
        for (int o = 1; o < 4; o <<= 1) {
            slo += __shfl_xor_sync(0xffffffffu, slo, o);
            shi += __shfl_xor_sync(0xffffffffu, shi, o);
        }
        if ((lane & 3) == 0) {
            s_red[rlo * 2 + wn] = slo;
            s_red[rhi * 2 + wn] = shi;
        }
    }
    __syncthreads();
    if (tid < BM) {
        float s = s_red[tid * 2 + 0] + s_red[tid * 2 + 1];
        g_pmax[(size_t)nt * Mtot + m0 + tid] = s_rowmax[tid];
        g_psum[(size_t)nt * Mtot + m0 + tid] = s;
    }
}

// ----------------------------------------------------------------------------
// Coalesced logZ combine: 1 block per 32 tokens, 256 threads (8 nt-slices x
// 32 tokens). Each 32-thread group reads a full 128B line. Online LSE merge.
// grid = 128.
// ----------------------------------------------------------------------------
__global__ __launch_bounds__(256) void reduce_lz_kernel()
{
    __shared__ float s_mx[8][32];
    __shared__ float s_sv[8][32];
    const int tid = threadIdx.x;
    const int tg  = tid >> 5;            // nt-slice 0..7
    const int ml  = tid & 31;            // token within group
    const int m   = blockIdx.x * 32 + ml;

#pragma unroll
    for (int mat = 0; mat < 2; mat++) {
        const int base = mat * NT_PER;
        float mx = -1e30f, sv = 0.f;
        for (int nt = tg; nt < NT_PER; nt += 8) {
            const float p  = g_pmax[(size_t)(base + nt) * Mtot + m];
            const float ps = g_psum[(size_t)(base + nt) * Mtot + m];
            const float nm = fmaxf(mx, p);
            sv = sv * __expf(mx - nm) + ps * __expf(p - nm);
            mx = nm;
        }
        s_mx[tg][ml] = mx;
        s_sv[tg][ml] = sv;
        __syncthreads();
        if (tid < 32) {
            float M = -1e30f, S = 0.f;
#pragma unroll
            for (int g = 0; g < 8; g++) {
                const float p = s_mx[g][tid], ps = s_sv[g][tid];
                const float nm = fmaxf(M, p);
                S = S * __expf(M - nm) + ps * __expf(p - nm);
                M = nm;
            }
            const float lz = M + logf(S);
            if (mat == 0) g_lzW[m] = lz; else g_lzR[m] = lz;
        }
        __syncthreads();
    }
}

// ----------------------------------------------------------------------------
// Final DPO scalar. one block of 512
// ----------------------------------------------------------------------------
__global__ void final_kernel(const void* __restrict__ y, float* __restrict__ out)
{
    __shared__ float red[512];
    __shared__ float pav[8], rav[8];
    const int tid = threadIdx.x;
    for (int b = 0; b < 8; b++) {
        const int m = b * 512 + tid;
        const int yv = get_label(y, m);
        const bool v = (yv != -100);
        const float p = v ? (g_tokW[m] - g_lzW[m]) : 0.f;
        const float r = v ? (g_tokR[m] - g_lzR[m]) : 0.f;
        const float c = v ? 1.f : 0.f;

        red[tid] = p; __syncthreads();
        for (int s = 256; s > 0; s >>= 1) { if (tid < s) red[tid] += red[tid + s]; __syncthreads(); }
        float ps = red[0]; __syncthreads();

        red[tid] = r; __syncthreads();
        for (int s = 256; s > 0; s >>= 1) { if (tid < s) red[tid] += red[tid + s]; __syncthreads(); }
        float rs = red[0]; __syncthreads();

        red[tid] = c; __syncthreads();
        for (int s = 256; s > 0; s >>= 1) { if (tid < s) red[tid] += red[tid + s]; __syncthreads(); }
        float cs = red[0]; __syncthreads();

        if (tid == 0) { pav[b] = ps / cs; rav[b] = rs / cs; }
        __syncthreads();
    }
    if (tid == 0) {
        float loss = 0.f;
#pragma unroll
        for (int i = 0; i < 4; i++) {
            float z = 0.1f * ((pav[i] - rav[i]) - (pav[i + 4] - rav[i + 4]));
            loss += log1pf(expf(-z));
        }
        out[0] = loss * 0.25f;
    }
}

// ----------------------------------------------------------------------------
extern "C" void kernel_launch(void* const* d_in, const int* in_sizes, int n_in,
                              void* d_out, int out_size)
{
    const float* x = nullptr;
    const void*  y = nullptr;
    const float* Wm[2] = {nullptr, nullptr};
    int wcount = 0;
    for (int i = 0; i < n_in; i++) {
        if (in_sizes[i] == 16777216)                          x = (const float*)d_in[i];
        else if (in_sizes[i] == 4096 || in_sizes[i] == 8192)  y = d_in[i];
        else if (wcount < 2)                                  Wm[wcount++] = (const float*)d_in[i];
    }
    if (!x)      x     = (const float*)d_in[0];
    if (!y)      y     = d_in[1];
    if (!Wm[0])  Wm[0] = (const float*)d_in[2];
    if (!Wm[1])  Wm[1] = (const float*)d_in[3];
    const float* W    = Wm[0];
    const float* refW = Wm[1];

    cudaFuncSetAttribute(lse_kernel, cudaFuncAttributeMaxDynamicSharedMemorySize, DSMEM);

    detect_y_kernel<<<1, 32>>>((const int*)y);
    convert_tok_kernel<<<CONV_BLOCKS + TOK_BLOCKS, 256>>>(x, W, refW, y);

    dim3 grid(Mtot / BM, NT_TOT);   // (32 [fast: x L2-resident], 500)
    lse_kernel<<<grid, THREADS, DSMEM>>>();

    reduce_lz_kernel<<<Mtot / 32, 256>>>();
    final_kernel<<<1, 512>>>(y, (float*)d_out);
}

// round 13
// speedup vs baseline: 1.1281x; 1.0030x over previous
#include <cuda_runtime.h>
#include <cuda_bf16.h>
#include <cstdint>

// ----------------------------------------------------------------------------
// DPO loss on GB300 (sm_103 base target — legacy bf16 HMMA, rt=8 ceiling).
// Round 13: R12 winner + tail polish (reduce_lz 512 threads; shuffle-based
// final_kernel). lse/convert byte-identical to R12.
// ----------------------------------------------------------------------------

#define BM 128
#define BN 128
#define KC 64                 // K elems per stage: 128B rows (SW128 swizzle)
#define NSTAGE 3
#define THREADS 128

static constexpr int Hdim   = 4096;
static constexpr int Mtot   = 4096;          // 8*512 tokens
static constexpr int Vdim   = 32000;
static constexpr int NT_PER = Vdim / BN;     // 250 N-tiles per matrix
static constexpr int NT_TOT = 2 * NT_PER;    // 500
static constexpr int NKT    = Hdim / KC;     // 64 k-chunks

static constexpr int A_BYTES  = BM * 128;    // 16 KB
static constexpr int B_BYTES  = BN * 128;    // 16 KB
static constexpr int STAGE_B  = A_BYTES + B_BYTES;          // 32 KB
static constexpr int DSMEM    = 1024 + NSTAGE * STAGE_B;    // ~97 KB

// ---------------- scratch (allocation-free __device__ globals) ----------------
__device__ __nv_bfloat16 g_xbf[(size_t)Mtot * Hdim];   //  33.5 MB
__device__ __nv_bfloat16 g_wbf[(size_t)Vdim * Hdim];   // 262 MB
__device__ __nv_bfloat16 g_rbf[(size_t)Vdim * Hdim];   // 262 MB
__device__ float g_pmax[NT_TOT * Mtot];
__device__ float g_psum[NT_TOT * Mtot];
__device__ float g_tokW[Mtot];
__device__ float g_tokR[Mtot];
__device__ float g_lzW[Mtot];
__device__ float g_lzR[Mtot];
__device__ int   g_y_is64;

__device__ __forceinline__ uint32_t smem_u32(const void* p) {
    return (uint32_t)__cvta_generic_to_shared(p);
}
__device__ __forceinline__ void cp_async16(uint32_t dst, const void* src) {
    asm volatile("cp.async.cg.shared.global [%0], [%1], 16;\n" :: "r"(dst), "l"(src));
}
#define SWZ(x) ((x) ^ (((x) >> 3) & 0x70))

// label accessor, safe under int32 or int64 storage
__device__ __forceinline__ int get_label(const void* y, int m) {
    if (g_y_is64) return (int)((const long long*)y)[m];
    return ((const int*)y)[m];
}

// ----------------------------------------------------------------------------
__global__ void detect_y_kernel(const int* __restrict__ y32)
{
    if (threadIdx.x == 0) {
        int is64 = 1;
        for (int i = 0; i < 64; i++) {
            int hi = y32[2 * i + 1];
            if (hi != 0 && hi != -1) { is64 = 0; break; }
        }
        g_y_is64 = is64;
    }
}

// ----------------------------------------------------------------------------
// Fused: fp32 -> bf16 convert (blocks 0..4095) + exact token logits (blocks
// 4096..4607; 8 warps x 1 token each = 4096 tokens).
// ----------------------------------------------------------------------------
static constexpr size_t N8_X = (size_t)Mtot * Hdim / 8;
static constexpr size_t N8_W = (size_t)Vdim * Hdim / 8;
static constexpr size_t N8_TOT = N8_X + 2 * N8_W;
static constexpr int CONV_BLOCKS = 4096;
static constexpr int TOK_BLOCKS  = Mtot / 8;   // 512

__global__ __launch_bounds__(256) void convert_tok_kernel(
    const float* __restrict__ x, const float* __restrict__ W,
    const float* __restrict__ R, const void* __restrict__ y)
{
    if (blockIdx.x < CONV_BLOCKS) {
        size_t i = (size_t)blockIdx.x * blockDim.x + threadIdx.x;
        const size_t stride = (size_t)CONV_BLOCKS * blockDim.x;
        for (; i < N8_TOT; i += stride) {
            const float* src;
            __nv_bfloat16* dst;
            size_t j;
            if (i < N8_X)               { src = x; dst = g_xbf; j = i; }
            else if (i < N8_X + N8_W)   { src = W; dst = g_wbf; j = i - N8_X; }
            else                        { src = R; dst = g_rbf; j = i - N8_X - N8_W; }
            const float4* s = reinterpret_cast<const float4*>(src) + 2 * j;
            float4 a = s[0], b = s[1];
            __nv_bfloat162 o[4] = {
                __floats2bfloat162_rn(a.x, a.y), __floats2bfloat162_rn(a.z, a.w),
                __floats2bfloat162_rn(b.x, b.y), __floats2bfloat162_rn(b.z, b.w)};
            *reinterpret_cast<uint4*>(dst + j * 8) = *reinterpret_cast<const uint4*>(o);
        }
    } else {
        // token-logit blocks: one warp per token, fp32 exact
        const int blk  = blockIdx.x - CONV_BLOCKS;      // 0..511
        const int warp = threadIdx.x >> 5, lane = threadIdx.x & 31;
        const int m = blk * 8 + warp;
        int idx = get_label(y, m);
        if (idx < 0 || idx >= Vdim) idx = 0;            // defensive clamp
        const float4* xr = reinterpret_cast<const float4*>(x + (size_t)m   * Hdim);
        const float4* wr = reinterpret_cast<const float4*>(W + (size_t)idx * Hdim);
        const float4* rr = reinterpret_cast<const float4*>(R + (size_t)idx * Hdim);
        float sw = 0.f, sr = 0.f;
        for (int j = lane; j < Hdim / 4; j += 32) {
            float4 a = xr[j], b = wr[j], c = rr[j];
            sw += a.x * b.x + a.y * b.y + a.z * b.z + a.w * b.w;
            sr += a.x * c.x + a.y * c.y + a.z * c.z + a.w * c.w;
        }
#pragma unroll
        for (int o = 16; o > 0; o >>= 1) {
            sw += __shfl_xor_sync(0xffffffffu, sw, o);
            sr += __shfl_xor_sync(0xffffffffu, sr, o);
        }
        if (lane == 0) { g_tokW[m] = sw; g_tokR[m] = sr; }
    }
}

// ----------------------------------------------------------------------------
// Main GEMM + online LSE epilogue. grid=(32 mt [fast], 500 nt), block=128.
// 4 warps in a 2x2 (M x N) grid; each warp computes 64x64. (R10-R12 winner)
// ----------------------------------------------------------------------------
__global__ __launch_bounds__(THREADS, 2) void lse_kernel()
{
    extern __shared__ char dsm[];
    const uint32_t raw  = smem_u32(dsm);
    const uint32_t stg  = (raw + 1023) & ~1023u;   // 1024-aligned

    __shared__ float s_red[BM * 2];
    __shared__ float s_rowmax[BM];

    const int tid  = threadIdx.x;
    const int warp = tid >> 5, lane = tid & 31;
    const int wm   = warp >> 1, wn = warp & 1;     // 2 x 2 warp grid

    const int mt = blockIdx.x, nt = blockIdx.y;
    const int m0 = mt * BM;
    const int n0 = (nt < NT_PER ? nt : nt - NT_PER) * BN;
    const __nv_bfloat16* asrc = g_xbf + (size_t)m0 * Hdim;
    const __nv_bfloat16* bsrc = ((nt < NT_PER) ? g_wbf : g_rbf) + (size_t)n0 * Hdim;

    float acc[4][8][4];            // 128 fp32 accumulators / thread
#pragma unroll
    for (int i = 0; i < 4; i++)
#pragma unroll
        for (int j = 0; j < 8; j++)
#pragma unroll
            for (int c = 0; c < 4; c++) acc[i][j][c] = 0.f;

    auto load_stage = [&](int slot, int kt) {
        const uint32_t a_base = stg + slot * STAGE_B;
        const uint32_t b_base = a_base + A_BYTES;
        const int k0 = kt * KC;
#pragma unroll
        for (int i = 0; i < 8; i++) {
            int id  = tid + i * THREADS;      // 0..1023
            int row = id >> 3, c = id & 7;    // 128 rows x 8 chunks
            cp_async16(a_base + SWZ(row * 128 + c * 16),
                       asrc + (size_t)row * Hdim + k0 + c * 8);
            cp_async16(b_base + SWZ(row * 128 + c * 16),
                       bsrc + (size_t)row * Hdim + k0 + c * 8);
        }
        asm volatile("cp.async.commit_group;" ::: "memory");
    };

    auto compute = [&](int slot) {
        const uint32_t a_base = stg + slot * STAGE_B;
        const uint32_t b_base = a_base + A_BYTES;
#pragma unroll
        for (int ks = 0; ks < 4; ks++) {       // 4 x K=16 inside the 64 chunk
            uint32_t af[4][4], bf[8][2];
            const int arow = wm * 64 + (lane & 15);
            const int asel = (lane >> 4) & 1;
#pragma unroll
            for (int mi = 0; mi < 4; mi++) {
                uint32_t addr = a_base +
                    SWZ((uint32_t)(arow + mi * 16) * 128 + ks * 32 + asel * 16);
                asm volatile("ldmatrix.sync.aligned.m8n8.x4.shared.b16 {%0,%1,%2,%3}, [%4];"
                             : "=r"(af[mi][0]), "=r"(af[mi][1]),
                               "=r"(af[mi][2]), "=r"(af[mi][3])
                             : "r"(addr));
            }
            // B: x4 over pairs of 8-col groups.
#pragma unroll
            for (int np = 0; np < 4; np++) {
                const uint32_t brow = wn * 64 + np * 16 +
                                      ((lane >> 4) << 3) + (lane & 7);
                const uint32_t bsel = (lane >> 3) & 1;
                uint32_t addr = b_base + SWZ(brow * 128 + ks * 32 + bsel * 16);
                asm volatile("ldmatrix.sync.aligned.m8n8.x4.shared.b16 {%0,%1,%2,%3}, [%4];"
                             : "=r"(bf[2 * np][0]), "=r"(bf[2 * np][1]),
                               "=r"(bf[2 * np + 1][0]), "=r"(bf[2 * np + 1][1])
                             : "r"(addr));
            }
#pragma unroll
            for (int mi = 0; mi < 4; mi++)
#pragma unroll
                for (int ni = 0; ni < 8; ni++)
                    asm volatile(
                        "mma.sync.aligned.m16n8k16.row.col.f32.bf16.bf16.f32 "
                        "{%0,%1,%2,%3}, {%4,%5,%6,%7}, {%8,%9}, {%0,%1,%2,%3};"
                        : "+f"(acc[mi][ni][0]), "+f"(acc[mi][ni][1]),
                          "+f"(acc[mi][ni][2]), "+f"(acc[mi][ni][3])
                        : "r"(af[mi][0]), "r"(af[mi][1]), "r"(af[mi][2]), "r"(af[mi][3]),
                          "r"(bf[ni][0]), "r"(bf[ni][1]));
        }
    };

    // prologue: fill NSTAGE-1 stages
    load_stage(0, 0);
    load_stage(1, 1);

    for (int kt = 0; kt < NKT; kt++) {
        const int slot = kt % NSTAGE;
        if (kt + 2 < NKT) {
            asm volatile("cp.async.wait_group 1;" ::: "memory");
        } else {
            asm volatile("cp.async.wait_group 0;" ::: "memory");
        }
        __syncthreads();
        if (kt + 2 < NKT) load_stage((kt + 2) % NSTAGE, kt + 2);
        compute(slot);
    }

    // ---- fused epilogue: per-token max / sumexp over this 128-col tile ----
    const float NEG = -1e30f;
#pragma unroll
    for (int mi = 0; mi < 4; mi++) {
        float mlo = NEG, mhi = NEG;
#pragma unroll
        for (int ni = 0; ni < 8; ni++) {
            mlo = fmaxf(mlo, fmaxf(acc[mi][ni][0], acc[mi][ni][1]));
            mhi = fmaxf(mhi, fmaxf(acc[mi][ni][2], acc[mi][ni][3]));
        }
#pragma unroll
        for (int o = 1; o < 4; o <<= 1) {
            mlo = fmaxf(mlo, __shfl_xor_sync(0xffffffffu, mlo, o));
            mhi = fmaxf(mhi, __shfl_xor_sync(0xffffffffu, mhi, o));
        }
        if ((lane & 3) == 0) {
            int rlo = wm * 64 + mi * 16 + (lane >> 2);
            s_red[rlo * 2 + wn]       = mlo;
            s_red[(rlo + 8) * 2 + wn] = mhi;
        }
    }
    __syncthreads();
    if (tid < BM) {
        s_rowmax[tid] = fmaxf(s_red[tid * 2 + 0], s_red[tid * 2 + 1]);
    }
    __syncthreads();
#pragma unroll
    for (int mi = 0; mi < 4; mi++) {
        int rlo = wm * 64 + mi * 16 + (lane >> 2);
        int rhi = rlo + 8;
        float Mlo = s_rowmax[rlo], Mhi = s_rowmax[rhi];
        float slo = 0.f, shi = 0.f;
#pragma unroll
        for (int ni = 0; ni < 8; ni++) {
            slo += __expf(acc[mi][ni][0] - Mlo) + __expf(acc[mi][ni][1] - Mlo);
            shi += __expf(acc[mi][ni][2] - Mhi) + __expf(acc[mi][ni][3] - Mhi);
        }
#pragma unroll
        for (int o = 1; o < 4; o <<= 1) {
            slo += __shfl_xor_sync(0xffffffffu, slo, o);
            shi += __shfl_xor_sync(0xffffffffu, shi, o);
        }
        if ((lane & 3) == 0) {
            s_red[rlo * 2 + wn] = slo;
            s_red[rhi * 2 + wn] = shi;
        }
    }
    __syncthreads();
    if (tid < BM) {
        float s = s_red[tid * 2 + 0] + s_red[tid * 2 + 1];
        g_pmax[(size_t)nt * Mtot + m0 + tid] = s_rowmax[tid];
        g_psum[(size_t)nt * Mtot + m0 + tid] = s;
    }
}

// ----------------------------------------------------------------------------
// Coalesced logZ combine: 1 block per 32 tokens, 512 threads (16 nt-slices x
// 32 tokens). Each 32-thread group reads a full 128B line. Online LSE merge.
// grid = 128.
// ----------------------------------------------------------------------------
__global__ __launch_bounds__(512) void reduce_lz_kernel()
{
    __shared__ float s_mx[16][32];
    __shared__ float s_sv[16][32];
    const int tid = threadIdx.x;
    const int tg  = tid >> 5;            // nt-slice 0..15
    const int ml  = tid & 31;            // token within group
    const int m   = blockIdx.x * 32 + ml;

#pragma unroll
    for (int mat = 0; mat < 2; mat++) {
        const int base = mat * NT_PER;
        float mx = -1e30f, sv = 0.f;
        for (int nt = tg; nt < NT_PER; nt += 16) {
            const float p  = g_pmax[(size_t)(base + nt) * Mtot + m];
            const float ps = g_psum[(size_t)(base + nt) * Mtot + m];
            const float nm = fmaxf(mx, p);
            sv = sv * __expf(mx - nm) + ps * __expf(p - nm);
            mx = nm;
        }
        s_mx[tg][ml] = mx;
        s_sv[tg][ml] = sv;
        __syncthreads();
        if (tid < 32) {
            float M = -1e30f, S = 0.f;
#pragma unroll
            for (int g = 0; g < 16; g++) {
                const float p = s_mx[g][tid], ps = s_sv[g][tid];
                const float nm = fmaxf(M, p);
                S = S * __expf(M - nm) + ps * __expf(p - nm);
                M = nm;
            }
            const float lz = M + logf(S);
            if (mat == 0) g_lzW[m] = lz; else g_lzR[m] = lz;
        }
        __syncthreads();
    }
}

// ----------------------------------------------------------------------------
// Final DPO scalar. one block of 512; shuffle-based reductions (1 sync/batch).
// ----------------------------------------------------------------------------
__global__ __launch_bounds__(512) void final_kernel(const void* __restrict__ y,
                                                    float* __restrict__ out)
{
    __shared__ float s_p[16], s_r[16], s_c[16];
    __shared__ float pav[8], rav[8];
    const int tid  = threadIdx.x;
    const int warp = tid >> 5, lane = tid & 31;

    for (int b = 0; b < 8; b++) {
        const int m = b * 512 + tid;
        const int yv = get_label(y, m);
        const bool v = (yv != -100);
        float p = v ? (g_tokW[m] - g_lzW[m]) : 0.f;
        float r = v ? (g_tokR[m] - g_lzR[m]) : 0.f;
        float c = v ? 1.f : 0.f;
#pragma unroll
        for (int o = 16; o > 0; o >>= 1) {
            p += __shfl_xor_sync(0xffffffffu, p, o);
            r += __shfl_xor_sync(0xffffffffu, r, o);
            c += __shfl_xor_sync(0xffffffffu, c, o);
        }
        if (lane == 0) { s_p[warp] = p; s_r[warp] = r; s_c[warp] = c; }
        __syncthreads();
        if (tid == 0) {
            float ps = 0.f, rs = 0.f, cs = 0.f;
#pragma unroll
            for (int w = 0; w < 16; w++) { ps += s_p[w]; rs += s_r[w]; cs += s_c[w]; }
            pav[b] = ps / cs;
            rav[b] = rs / cs;
        }
        __syncthreads();
    }
    if (tid == 0) {
        float loss = 0.f;
#pragma unroll
        for (int i = 0; i < 4; i++) {
            float z = 0.1f * ((pav[i] - rav[i]) - (pav[i + 4] - rav[i + 4]));
            loss += log1pf(expf(-z));
        }
        out[0] = loss * 0.25f;
    }
}

// ----------------------------------------------------------------------------
extern "C" void kernel_launch(void* const* d_in, const int* in_sizes, int n_in,
                              void* d_out, int out_size)
{
    const float* x = nullptr;
    const void*  y = nullptr;
    const float* Wm[2] = {nullptr, nullptr};
    int wcount = 0;
    for (int i = 0; i < n_in; i++) {
        if (in_sizes[i] == 16777216)                          x = (const float*)d_in[i];
        else if (in_sizes[i] == 4096 || in_sizes[i] == 8192)  y = d_in[i];
        else if (wcount < 2)                                  Wm[wcount++] = (const float*)d_in[i];
    }
    if (!x)      x     = (const float*)d_in[0];
    if (!y)      y     = d_in[1];
    if (!Wm[0])  Wm[0] = (const float*)d_in[2];
    if (!Wm[1])  Wm[1] = (const float*)d_in[3];
    const float* W    = Wm[0];
    const float* refW = Wm[1];

    cudaFuncSetAttribute(lse_kernel, cudaFuncAttributeMaxDynamicSharedMemorySize, DSMEM);

    detect_y_kernel<<<1, 32>>>((const int*)y);
    convert_tok_kernel<<<CONV_BLOCKS + TOK_BLOCKS, 256>>>(x, W, refW, y);

    dim3 grid(Mtot / BM, NT_TOT);   // (32 [fast: x L2-resident], 500)
    lse_kernel<<<grid, THREADS, DSMEM>>>();

    reduce_lz_kernel<<<Mtot / 32, 512>>>();
    final_kernel<<<1, 512>>>(y, (float*)d_out);
}

// round 14
// speedup vs baseline: 1.1282x; 1.0000x over previous
#include <cuda_runtime.h>
#include <cuda_bf16.h>
#include <cstdint>

// ----------------------------------------------------------------------------
// DPO loss on GB300 (sm_103 base target — legacy bf16 HMMA, rt=8 ceiling).
// Round 14: R13 winner + reduce_lz at 1024 threads (32 slices x 32 tokens).
// lse/convert/final byte-identical to R13.
// ----------------------------------------------------------------------------

#define BM 128
#define BN 128
#define KC 64                 // K elems per stage: 128B rows (SW128 swizzle)
#define NSTAGE 3
#define THREADS 128

static constexpr int Hdim   = 4096;
static constexpr int Mtot   = 4096;          // 8*512 tokens
static constexpr int Vdim   = 32000;
static constexpr int NT_PER = Vdim / BN;     // 250 N-tiles per matrix
static constexpr int NT_TOT = 2 * NT_PER;    // 500
static constexpr int NKT    = Hdim / KC;     // 64 k-chunks

static constexpr int A_BYTES  = BM * 128;    // 16 KB
static constexpr int B_BYTES  = BN * 128;    // 16 KB
static constexpr int STAGE_B  = A_BYTES + B_BYTES;          // 32 KB
static constexpr int DSMEM    = 1024 + NSTAGE * STAGE_B;    // ~97 KB

// ---------------- scratch (allocation-free __device__ globals) ----------------
__device__ __nv_bfloat16 g_xbf[(size_t)Mtot * Hdim];   //  33.5 MB
__device__ __nv_bfloat16 g_wbf[(size_t)Vdim * Hdim];   // 262 MB
__device__ __nv_bfloat16 g_rbf[(size_t)Vdim * Hdim];   // 262 MB
__device__ float g_pmax[NT_TOT * Mtot];
__device__ float g_psum[NT_TOT * Mtot];
__device__ float g_tokW[Mtot];
__device__ float g_tokR[Mtot];
__device__ float g_lzW[Mtot];
__device__ float g_lzR[Mtot];
__device__ int   g_y_is64;

__device__ __forceinline__ uint32_t smem_u32(const void* p) {
    return (uint32_t)__cvta_generic_to_shared(p);
}
__device__ __forceinline__ void cp_async16(uint32_t dst, const void* src) {
    asm volatile("cp.async.cg.shared.global [%0], [%1], 16;\n" :: "r"(dst), "l"(src));
}
#define SWZ(x) ((x) ^ (((x) >> 3) & 0x70))

// label accessor, safe under int32 or int64 storage
__device__ __forceinline__ int get_label(const void* y, int m) {
    if (g_y_is64) return (int)((const long long*)y)[m];
    return ((const int*)y)[m];
}

// ----------------------------------------------------------------------------
__global__ void detect_y_kernel(const int* __restrict__ y32)
{
    if (threadIdx.x == 0) {
        int is64 = 1;
        for (int i = 0; i < 64; i++) {
            int hi = y32[2 * i + 1];
            if (hi != 0 && hi != -1) { is64 = 0; break; }
        }
        g_y_is64 = is64;
    }
}

// ----------------------------------------------------------------------------
// Fused: fp32 -> bf16 convert (blocks 0..4095) + exact token logits (blocks
// 4096..4607; 8 warps x 1 token each = 4096 tokens).
// ----------------------------------------------------------------------------
static constexpr size_t N8_X = (size_t)Mtot * Hdim / 8;
static constexpr size_t N8_W = (size_t)Vdim * Hdim / 8;
static constexpr size_t N8_TOT = N8_X + 2 * N8_W;
static constexpr int CONV_BLOCKS = 4096;
static constexpr int TOK_BLOCKS  = Mtot / 8;   // 512

__global__ __launch_bounds__(256) void convert_tok_kernel(
    const float* __restrict__ x, const float* __restrict__ W,
    const float* __restrict__ R, const void* __restrict__ y)
{
    if (blockIdx.x < CONV_BLOCKS) {
        size_t i = (size_t)blockIdx.x * blockDim.x + threadIdx.x;
        const size_t stride = (size_t)CONV_BLOCKS * blockDim.x;
        for (; i < N8_TOT; i += stride) {
            const float* src;
            __nv_bfloat16* dst;
            size_t j;
            if (i < N8_X)               { src = x; dst = g_xbf; j = i; }
            else if (i < N8_X + N8_W)   { src = W; dst = g_wbf; j = i - N8_X; }
            else                        { src = R; dst = g_rbf; j = i - N8_X - N8_W; }
            const float4* s = reinterpret_cast<const float4*>(src) + 2 * j;
            float4 a = s[0], b = s[1];
            __nv_bfloat162 o[4] = {
                __floats2bfloat162_rn(a.x, a.y), __floats2bfloat162_rn(a.z, a.w),
                __floats2bfloat162_rn(b.x, b.y), __floats2bfloat162_rn(b.z, b.w)};
            *reinterpret_cast<uint4*>(dst + j * 8) = *reinterpret_cast<const uint4*>(o);
        }
    } else {
        // token-logit blocks: one warp per token, fp32 exact
        const int blk  = blockIdx.x - CONV_BLOCKS;      // 0..511
        const int warp = threadIdx.x >> 5, lane = threadIdx.x & 31;
        const int m = blk * 8 + warp;
        int idx = get_label(y, m);
        if (idx < 0 || idx >= Vdim) idx = 0;            // defensive clamp
        const float4* xr = reinterpret_cast<const float4*>(x + (size_t)m   * Hdim);
        const float4* wr = reinterpret_cast<const float4*>(W + (size_t)idx * Hdim);
        const float4* rr = reinterpret_cast<const float4*>(R + (size_t)idx * Hdim);
        float sw = 0.f, sr = 0.f;
        for (int j = lane; j < Hdim / 4; j += 32) {
            float4 a = xr[j], b = wr[j], c = rr[j];
            sw += a.x * b.x + a.y * b.y + a.z * b.z + a.w * b.w;
            sr += a.x * c.x + a.y * c.y + a.z * c.z + a.w * c.w;
        }
#pragma unroll
        for (int o = 16; o > 0; o >>= 1) {
            sw += __shfl_xor_sync(0xffffffffu, sw, o);
            sr += __shfl_xor_sync(0xffffffffu, sr, o);
        }
        if (lane == 0) { g_tokW[m] = sw; g_tokR[m] = sr; }
    }
}

// ----------------------------------------------------------------------------
// Main GEMM + online LSE epilogue. grid=(32 mt [fast], 500 nt), block=128.
// 4 warps in a 2x2 (M x N) grid; each warp computes 64x64. (R10-R13 winner)
// ----------------------------------------------------------------------------
__global__ __launch_bounds__(THREADS, 2) void lse_kernel()
{
    extern __shared__ char dsm[];
    const uint32_t raw  = smem_u32(dsm);
    const uint32_t stg  = (raw + 1023) & ~1023u;   // 1024-aligned

    __shared__ float s_red[BM * 2];
    __shared__ float s_rowmax[BM];

    const int tid  = threadIdx.x;
    const int warp = tid >> 5, lane = tid & 31;
    const int wm   = warp >> 1, wn = warp & 1;     // 2 x 2 warp grid

    const int mt = blockIdx.x, nt = blockIdx.y;
    const int m0 = mt * BM;
    const int n0 = (nt < NT_PER ? nt : nt - NT_PER) * BN;
    const __nv_bfloat16* asrc = g_xbf + (size_t)m0 * Hdim;
    const __nv_bfloat16* bsrc = ((nt < NT_PER) ? g_wbf : g_rbf) + (size_t)n0 * Hdim;

    float acc[4][8][4];            // 128 fp32 accumulators / thread
#pragma unroll
    for (int i = 0; i < 4; i++)
#pragma unroll
        for (int j = 0; j < 8; j++)
#pragma unroll
            for (int c = 0; c < 4; c++) acc[i][j][c] = 0.f;

    auto load_stage = [&](int slot, int kt) {
        const uint32_t a_base = stg + slot * STAGE_B;
        const uint32_t b_base = a_base + A_BYTES;
        const int k0 = kt * KC;
#pragma unroll
        for (int i = 0; i < 8; i++) {
            int id  = tid + i * THREADS;      // 0..1023
            int row = id >> 3, c = id & 7;    // 128 rows x 8 chunks
            cp_async16(a_base + SWZ(row * 128 + c * 16),
                       asrc + (size_t)row * Hdim + k0 + c * 8);
            cp_async16(b_base + SWZ(row * 128 + c * 16),
                       bsrc + (size_t)row * Hdim + k0 + c * 8);
        }
        asm volatile("cp.async.commit_group;" ::: "memory");
    };

    auto compute = [&](int slot) {
        const uint32_t a_base = stg + slot * STAGE_B;
        const uint32_t b_base = a_base + A_BYTES;
#pragma unroll
        for (int ks = 0; ks < 4; ks++) {       // 4 x K=16 inside the 64 chunk
            uint32_t af[4][4], bf[8][2];
            const int arow = wm * 64 + (lane & 15);
            const int asel = (lane >> 4) & 1;
#pragma unroll
            for (int mi = 0; mi < 4; mi++) {
                uint32_t addr = a_base +
                    SWZ((uint32_t)(arow + mi * 16) * 128 + ks * 32 + asel * 16);
                asm volatile("ldmatrix.sync.aligned.m8n8.x4.shared.b16 {%0,%1,%2,%3}, [%4];"
                             : "=r"(af[mi][0]), "=r"(af[mi][1]),
                               "=r"(af[mi][2]), "=r"(af[mi][3])
                             : "r"(addr));
            }
            // B: x4 over pairs of 8-col groups.
#pragma unroll
            for (int np = 0; np < 4; np++) {
                const uint32_t brow = wn * 64 + np * 16 +
                                      ((lane >> 4) << 3) + (lane & 7);
                const uint32_t bsel = (lane >> 3) & 1;
                uint32_t addr = b_base + SWZ(brow * 128 + ks * 32 + bsel * 16);
                asm volatile("ldmatrix.sync.aligned.m8n8.x4.shared.b16 {%0,%1,%2,%3}, [%4];"
                             : "=r"(bf[2 * np][0]), "=r"(bf[2 * np][1]),
                               "=r"(bf[2 * np + 1][0]), "=r"(bf[2 * np + 1][1])
                             : "r"(addr));
            }
#pragma unroll
            for (int mi = 0; mi < 4; mi++)
#pragma unroll
                for (int ni = 0; ni < 8; ni++)
                    asm volatile(
                        "mma.sync.aligned.m16n8k16.row.col.f32.bf16.bf16.f32 "
                        "{%0,%1,%2,%3}, {%4,%5,%6,%7}, {%8,%9}, {%0,%1,%2,%3};"
                        : "+f"(acc[mi][ni][0]), "+f"(acc[mi][ni][1]),
                          "+f"(acc[mi][ni][2]), "+f"(acc[mi][ni][3])
                        : "r"(af[mi][0]), "r"(af[mi][1]), "r"(af[mi][2]), "r"(af[mi][3]),
                          "r"(bf[ni][0]), "r"(bf[ni][1]));
        }
    };

    // prologue: fill NSTAGE-1 stages
    load_stage(0, 0);
    load_stage(1, 1);

    for (int kt = 0; kt < NKT; kt++) {
        const int slot = kt % NSTAGE;
        if (kt + 2 < NKT) {
            asm volatile("cp.async.wait_group 1;" ::: "memory");
        } else {
            asm volatile("cp.async.wait_group 0;" ::: "memory");
        }
        __syncthreads();
        if (kt + 2 < NKT) load_stage((kt + 2) % NSTAGE, kt + 2);
        compute(slot);
    }

    // ---- fused epilogue: per-token max / sumexp over this 128-col tile ----
    const float NEG = -1e30f;
#pragma unroll
    for (int mi = 0; mi < 4; mi++) {
        float mlo = NEG, mhi = NEG;
#pragma unroll
        for (int ni = 0; ni < 8; ni++) {
            mlo = fmaxf(mlo, fmaxf(acc[mi][ni][0], acc[mi][ni][1]));
            mhi = fmaxf(mhi, fmaxf(acc[mi][ni][2], acc[mi][ni][3]));
        }
#pragma unroll
        for (int o = 1; o < 4; o <<= 1) {
            mlo = fmaxf(mlo, __shfl_xor_sync(0xffffffffu, mlo, o));
            mhi = fmaxf(mhi, __shfl_xor_sync(0xffffffffu, mhi, o));
        }
        if ((lane & 3) == 0) {
            int rlo = wm * 64 + mi * 16 + (lane >> 2);
            s_red[rlo * 2 + wn]       = mlo;
            s_red[(rlo + 8) * 2 + wn] = mhi;
        }
    }
    __syncthreads();
    if (tid < BM) {
        s_rowmax[tid] = fmaxf(s_red[tid * 2 + 0], s_red[tid * 2 + 1]);
    }
    __syncthreads();
#pragma unroll
    for (int mi = 0; mi < 4; mi++) {
        int rlo = wm * 64 + mi * 16 + (lane >> 2);
        int rhi = rlo + 8;
        float Mlo = s_rowmax[rlo], Mhi = s_rowmax[rhi];
        float slo = 0.f, shi = 0.f;
#pragma unroll
        for (int ni = 0; ni < 8; ni++) {
            slo += __expf(acc[mi][ni][0] - Mlo) + __expf(acc[mi][ni][1] - Mlo);
            shi += __expf(acc[mi][ni][2] - Mhi) + __expf(acc[mi][ni][3] - Mhi);
        }
#pragma unroll
        for (int o = 1; o < 4; o <<= 1) {
            slo += __shfl_xor_sync(0xffffffffu, slo, o);
            shi += __shfl_xor_sync(0xffffffffu, shi, o);
        }
        if ((lane & 3) == 0) {
            s_red[rlo * 2 + wn] = slo;
            s_red[rhi * 2 + wn] = shi;
        }
    }
    __syncthreads();
    if (tid < BM) {
        float s = s_red[tid * 2 + 0] + s_red[tid * 2 + 1];
        g_pmax[(size_t)nt * Mtot + m0 + tid] = s_rowmax[tid];
        g_psum[(size_t)nt * Mtot + m0 + tid] = s;
    }
}

// ----------------------------------------------------------------------------
// Coalesced logZ combine: 1 block per 32 tokens, 1024 threads (32 nt-slices x
// 32 tokens). Each 32-thread group reads a full 128B line. Online LSE merge.
// grid = 128.
// ----------------------------------------------------------------------------
__global__ __launch_bounds__(1024) void reduce_lz_kernel()
{
    __shared__ float s_mx[32][32];
    __shared__ float s_sv[32][32];
    const int tid = threadIdx.x;
    const int tg  = tid >> 5;            // nt-slice 0..31
    const int ml  = tid & 31;            // token within group
    const int m   = blockIdx.x * 32 + ml;

#pragma unroll
    for (int mat = 0; mat < 2; mat++) {
        const int base = mat * NT_PER;
        float mx = -1e30f, sv = 0.f;
        for (int nt = tg; nt < NT_PER; nt += 32) {
            const float p  = g_pmax[(size_t)(base + nt) * Mtot + m];
            const float ps = g_psum[(size_t)(base + nt) * Mtot + m];
            const float nm = fmaxf(mx, p);
            sv = sv * __expf(mx - nm) + ps * __expf(p - nm);
            mx = nm;
        }
        s_mx[tg][ml] = mx;
        s_sv[tg][ml] = sv;
        __syncthreads();
        if (tid < 32) {
            float M = -1e30f, S = 0.f;
#pragma unroll
            for (int g = 0; g < 32; g++) {
                const float p = s_mx[g][tid], ps = s_sv[g][tid];
                const float nm = fmaxf(M, p);
                S = S * __expf(M - nm) + ps * __expf(p - nm);
                M = nm;
            }
            const float lz = M + logf(S);
            if (mat == 0) g_lzW[m] = lz; else g_lzR[m] = lz;
        }
        __syncthreads();
    }
}

// ----------------------------------------------------------------------------
// Final DPO scalar. one block of 512; shuffle-based reductions (1 sync/batch).
// ----------------------------------------------------------------------------
__global__ __launch_bounds__(512) void final_kernel(const void* __restrict__ y,
                                                    float* __restrict__ out)
{
    __shared__ float s_p[16], s_r[16], s_c[16];
    __shared__ float pav[8], rav[8];
    const int tid  = threadIdx.x;
    const int warp = tid >> 5, lane = tid & 31;

    for (int b = 0; b < 8; b++) {
        const int m = b * 512 + tid;
        const int yv = get_label(y, m);
        const bool v = (yv != -100);
        float p = v ? (g_tokW[m] - g_lzW[m]) : 0.f;
        float r = v ? (g_tokR[m] - g_lzR[m]) : 0.f;
        float c = v ? 1.f : 0.f;
#pragma unroll
        for (int o = 16; o > 0; o >>= 1) {
            p += __shfl_xor_sync(0xffffffffu, p, o);
            r += __shfl_xor_sync(0xffffffffu, r, o);
            c += __shfl_xor_sync(0xffffffffu, c, o);
        }
        if (lane == 0) { s_p[warp] = p; s_r[warp] = r; s_c[warp] = c; }
        __syncthreads();
        if (tid == 0) {
            float ps = 0.f, rs = 0.f, cs = 0.f;
#pragma unroll
            for (int w = 0; w < 16; w++) { ps += s_p[w]; rs += s_r[w]; cs += s_c[w]; }
            pav[b] = ps / cs;
            rav[b] = rs / cs;
        }
        __syncthreads();
    }
    if (tid == 0) {
        float loss = 0.f;
#pragma unroll
        for (int i = 0; i < 4; i++) {
            float z = 0.1f * ((pav[i] - rav[i]) - (pav[i + 4] - rav[i + 4]));
            loss += log1pf(expf(-z));
        }
        out[0] = loss * 0.25f;
    }
}

// ----------------------------------------------------------------------------
extern "C" void kernel_launch(void* const* d_in, const int* in_sizes, int n_in,
                              void* d_out, int out_size)
{
    const float* x = nullptr;
    const void*  y = nullptr;
    const float* Wm[2] = {nullptr, nullptr};
    int wcount = 0;
    for (int i = 0; i < n_in; i++) {
        if (in_sizes[i] == 16777216)                          x = (const float*)d_in[i];
        else if (in_sizes[i] == 4096 || in_sizes[i] == 8192)  y = d_in[i];
        else if (wcount < 2)                                  Wm[wcount++] = (const float*)d_in[i];
    }
    if (!x)      x     = (const float*)d_in[0];
    if (!y)      y     = d_in[1];
    if (!Wm[0])  Wm[0] = (const float*)d_in[2];
    if (!Wm[1])  Wm[1] = (const float*)d_in[3];
    const float* W    = Wm[0];
    const float* refW = Wm[1];

    cudaFuncSetAttribute(lse_kernel, cudaFuncAttributeMaxDynamicSharedMemorySize, DSMEM);

    detect_y_kernel<<<1, 32>>>((const int*)y);
    convert_tok_kernel<<<CONV_BLOCKS + TOK_BLOCKS, 256>>>(x, W, refW, y);

    dim3 grid(Mtot / BM, NT_TOT);   // (32 [fast: x L2-resident], 500)
    lse_kernel<<<grid, THREADS, DSMEM>>>();

    reduce_lz_kernel<<<Mtot / 32, 1024>>>();
    final_kernel<<<1, 512>>>(y, (float*)d_out);
}

// round 15
// speedup vs baseline: 1.1284x; 1.0002x over previous
#include <cuda_runtime.h>
#include <cuda_bf16.h>
#include <cstdint>

// ----------------------------------------------------------------------------
// DPO loss on GB300 (sm_103 base target — legacy bf16 HMMA, rt=8 ceiling).
// Round 15 (final): R13/R14 champion + inlined y-dtype detection (one fewer
// launch). lse/convert/reduce_lz/final otherwise byte-identical.
// ----------------------------------------------------------------------------

#define BM 128
#define BN 128
#define KC 64                 // K elems per stage: 128B rows (SW128 swizzle)
#define NSTAGE 3
#define THREADS 128

static constexpr int Hdim   = 4096;
static constexpr int Mtot   = 4096;          // 8*512 tokens
static constexpr int Vdim   = 32000;
static constexpr int NT_PER = Vdim / BN;     // 250 N-tiles per matrix
static constexpr int NT_TOT = 2 * NT_PER;    // 500
static constexpr int NKT    = Hdim / KC;     // 64 k-chunks

static constexpr int A_BYTES  = BM * 128;    // 16 KB
static constexpr int B_BYTES  = BN * 128;    // 16 KB
static constexpr int STAGE_B  = A_BYTES + B_BYTES;          // 32 KB
static constexpr int DSMEM    = 1024 + NSTAGE * STAGE_B;    // ~97 KB

// ---------------- scratch (allocation-free __device__ globals) ----------------
__device__ __nv_bfloat16 g_xbf[(size_t)Mtot * Hdim];   //  33.5 MB
__device__ __nv_bfloat16 g_wbf[(size_t)Vdim * Hdim];   // 262 MB
__device__ __nv_bfloat16 g_rbf[(size_t)Vdim * Hdim];   // 262 MB
__device__ float g_pmax[NT_TOT * Mtot];
__device__ float g_psum[NT_TOT * Mtot];
__device__ float g_tokW[Mtot];
__device__ float g_tokR[Mtot];
__device__ float g_lzW[Mtot];
__device__ float g_lzR[Mtot];

__device__ __forceinline__ uint32_t smem_u32(const void* p) {
    return (uint32_t)__cvta_generic_to_shared(p);
}
__device__ __forceinline__ void cp_async16(uint32_t dst, const void* src) {
    asm volatile("cp.async.cg.shared.global [%0], [%1], 16;\n" :: "r"(dst), "l"(src));
}
#define SWZ(x) ((x) ^ (((x) >> 3) & 0x70))

// Inline y-dtype detection: int64 labels have high word 0 / -1 (incl. -100).
// Reads only the first 512 bytes — in range under either layout. Deterministic,
// so every caller computes the same answer; no cross-kernel ordering needed.
__device__ __forceinline__ int y_is64(const void* y) {
    const int* y32 = (const int*)y;
    int is64 = 1;
#pragma unroll 8
    for (int i = 0; i < 64; i++) {
        int hi = y32[2 * i + 1];
        if (hi != 0 && hi != -1) { is64 = 0; break; }
    }
    return is64;
}
__device__ __forceinline__ int get_label(const void* y, int m, int is64) {
    if (is64) return (int)((const long long*)y)[m];
    return ((const int*)y)[m];
}

// ----------------------------------------------------------------------------
// Fused: fp32 -> bf16 convert (blocks 0..4095) + exact token logits (blocks
// 4096..4607; 8 warps x 1 token each = 4096 tokens).
// ----------------------------------------------------------------------------
static constexpr size_t N8_X = (size_t)Mtot * Hdim / 8;
static constexpr size_t N8_W = (size_t)Vdim * Hdim / 8;
static constexpr size_t N8_TOT = N8_X + 2 * N8_W;
static constexpr int CONV_BLOCKS = 4096;
static constexpr int TOK_BLOCKS  = Mtot / 8;   // 512

__global__ __launch_bounds__(256) void convert_tok_kernel(
    const float* __restrict__ x, const float* __restrict__ W,
    const float* __restrict__ R, const void* __restrict__ y)
{
    if (blockIdx.x < CONV_BLOCKS) {
        size_t i = (size_t)blockIdx.x * blockDim.x + threadIdx.x;
        const size_t stride = (size_t)CONV_BLOCKS * blockDim.x;
        for (; i < N8_TOT; i += stride) {
            const float* src;
            __nv_bfloat16* dst;
            size_t j;
            if (i < N8_X)               { src = x; dst = g_xbf; j = i; }
            else if (i < N8_X + N8_W)   { src = W; dst = g_wbf; j = i - N8_X; }
            else                        { src = R; dst = g_rbf; j = i - N8_X - N8_W; }
            const float4* s = reinterpret_cast<const float4*>(src) + 2 * j;
            float4 a = s[0], b = s[1];
            __nv_bfloat162 o[4] = {
                __floats2bfloat162_rn(a.x, a.y), __floats2bfloat162_rn(a.z, a.w),
                __floats2bfloat162_rn(b.x, b.y), __floats2bfloat162_rn(b.z, b.w)};
            *reinterpret_cast<uint4*>(dst + j * 8) = *reinterpret_cast<const uint4*>(o);
        }
    } else {
        // token-logit blocks: one warp per token, fp32 exact
        const int blk  = blockIdx.x - CONV_BLOCKS;      // 0..511
        const int warp = threadIdx.x >> 5, lane = threadIdx.x & 31;
        const int m = blk * 8 + warp;
        const int is64 = y_is64(y);
        int idx = get_label(y, m, is64);
        if (idx < 0 || idx >= Vdim) idx = 0;            // defensive clamp
        const float4* xr = reinterpret_cast<const float4*>(x + (size_t)m   * Hdim);
        const float4* wr = reinterpret_cast<const float4*>(W + (size_t)idx * Hdim);
        const float4* rr = reinterpret_cast<const float4*>(R + (size_t)idx * Hdim);
        float sw = 0.f, sr = 0.f;
        for (int j = lane; j < Hdim / 4; j += 32) {
            float4 a = xr[j], b = wr[j], c = rr[j];
            sw += a.x * b.x + a.y * b.y + a.z * b.z + a.w * b.w;
            sr += a.x * c.x + a.y * c.y + a.z * c.z + a.w * c.w;
        }
#pragma unroll
        for (int o = 16; o > 0; o >>= 1) {
            sw += __shfl_xor_sync(0xffffffffu, sw, o);
            sr += __shfl_xor_sync(0xffffffffu, sr, o);
        }
        if (lane == 0) { g_tokW[m] = sw; g_tokR[m] = sr; }
    }
}

// ----------------------------------------------------------------------------
// Main GEMM + online LSE epilogue. grid=(32 mt [fast], 500 nt), block=128.
// 4 warps in a 2x2 (M x N) grid; each warp computes 64x64. (champion mainloop)
// ----------------------------------------------------------------------------
__global__ __launch_bounds__(THREADS, 2) void lse_kernel()
{
    extern __shared__ char dsm[];
    const uint32_t raw  = smem_u32(dsm);
    const uint32_t stg  = (raw + 1023) & ~1023u;   // 1024-aligned

    __shared__ float s_red[BM * 2];
    __shared__ float s_rowmax[BM];

    const int tid  = threadIdx.x;
    const int warp = tid >> 5, lane = tid & 31;
    const int wm   = warp >> 1, wn = warp & 1;     // 2 x 2 warp grid

    const int mt = blockIdx.x, nt = blockIdx.y;
    const int m0 = mt * BM;
    const int n0 = (nt < NT_PER ? nt : nt - NT_PER) * BN;
    const __nv_bfloat16* asrc = g_xbf + (size_t)m0 * Hdim;
    const __nv_bfloat16* bsrc = ((nt < NT_PER) ? g_wbf : g_rbf) + (size_t)n0 * Hdim;

    float acc[4][8][4];            // 128 fp32 accumulators / thread
#pragma unroll
    for (int i = 0; i < 4; i++)
#pragma unroll
        for (int j = 0; j < 8; j++)
#pragma unroll
            for (int c = 0; c < 4; c++) acc[i][j][c] = 0.f;

    auto load_stage = [&](int slot, int kt) {
        const uint32_t a_base = stg + slot * STAGE_B;
        const uint32_t b_base = a_base + A_BYTES;
        const int k0 = kt * KC;
#pragma unroll
        for (int i = 0; i < 8; i++) {
            int id  = tid + i * THREADS;      // 0..1023
            int row = id >> 3, c = id & 7;    // 128 rows x 8 chunks
            cp_async16(a_base + SWZ(row * 128 + c * 16),
                       asrc + (size_t)row * Hdim + k0 + c * 8);
            cp_async16(b_base + SWZ(row * 128 + c * 16),
                       bsrc + (size_t)row * Hdim + k0 + c * 8);
        }
        asm volatile("cp.async.commit_group;" ::: "memory");
    };

    auto compute = [&](int slot) {
        const uint32_t a_base = stg + slot * STAGE_B;
        const uint32_t b_base = a_base + A_BYTES;
#pragma unroll
        for (int ks = 0; ks < 4; ks++) {       // 4 x K=16 inside the 64 chunk
            uint32_t af[4][4], bf[8][2];
            const int arow = wm * 64 + (lane & 15);
            const int asel = (lane >> 4) & 1;
#pragma unroll
            for (int mi = 0; mi < 4; mi++) {
                uint32_t addr = a_base +
                    SWZ((uint32_t)(arow + mi * 16) * 128 + ks * 32 + asel * 16);
                asm volatile("ldmatrix.sync.aligned.m8n8.x4.shared.b16 {%0,%1,%2,%3}, [%4];"
                             : "=r"(af[mi][0]), "=r"(af[mi][1]),
                               "=r"(af[mi][2]), "=r"(af[mi][3])
                             : "r"(addr));
            }
            // B: x4 over pairs of 8-col groups.
#pragma unroll
            for (int np = 0; np < 4; np++) {
                const uint32_t brow = wn * 64 + np * 16 +
                                      ((lane >> 4) << 3) + (lane & 7);
                const uint32_t bsel = (lane >> 3) & 1;
                uint32_t addr = b_base + SWZ(brow * 128 + ks * 32 + bsel * 16);
                asm volatile("ldmatrix.sync.aligned.m8n8.x4.shared.b16 {%0,%1,%2,%3}, [%4];"
                             : "=r"(bf[2 * np][0]), "=r"(bf[2 * np][1]),
                               "=r"(bf[2 * np + 1][0]), "=r"(bf[2 * np + 1][1])
                             : "r"(addr));
            }
#pragma unroll
            for (int mi = 0; mi < 4; mi++)
#pragma unroll
                for (int ni = 0; ni < 8; ni++)
                    asm volatile(
                        "mma.sync.aligned.m16n8k16.row.col.f32.bf16.bf16.f32 "
                        "{%0,%1,%2,%3}, {%4,%5,%6,%7}, {%8,%9}, {%0,%1,%2,%3};"
                        : "+f"(acc[mi][ni][0]), "+f"(acc[mi][ni][1]),
                          "+f"(acc[mi][ni][2]), "+f"(acc[mi][ni][3])
                        : "r"(af[mi][0]), "r"(af[mi][1]), "r"(af[mi][2]), "r"(af[mi][3]),
                          "r"(bf[ni][0]), "r"(bf[ni][1]));
        }
    };

    // prologue: fill NSTAGE-1 stages
    load_stage(0, 0);
    load_stage(1, 1);

    for (int kt = 0; kt < NKT; kt++) {
        const int slot = kt % NSTAGE;
        if (kt + 2 < NKT) {
            asm volatile("cp.async.wait_group 1;" ::: "memory");
        } else {
            asm volatile("cp.async.wait_group 0;" ::: "memory");
        }
        __syncthreads();
        if (kt + 2 < NKT) load_stage((kt + 2) % NSTAGE, kt + 2);
        compute(slot);
    }

    // ---- fused epilogue: per-token max / sumexp over this 128-col tile ----
    const float NEG = -1e30f;
#pragma unroll
    for (int mi = 0; mi < 4; mi++) {
        float mlo = NEG, mhi = NEG;
#pragma unroll
        for (int ni = 0; ni < 8; ni++) {
            mlo = fmaxf(mlo, fmaxf(acc[mi][ni][0], acc[mi][ni][1]));
            mhi = fmaxf(mhi, fmaxf(acc[mi][ni][2], acc[mi][ni][3]));
        }
#pragma unroll
        for (int o = 1; o < 4; o <<= 1) {
            mlo = fmaxf(mlo, __shfl_xor_sync(0xffffffffu, mlo, o));
            mhi = fmaxf(mhi, __shfl_xor_sync(0xffffffffu, mhi, o));
        }
        if ((lane & 3) == 0) {
            int rlo = wm * 64 + mi * 16 + (lane >> 2);
            s_red[rlo * 2 + wn]       = mlo;
            s_red[(rlo + 8) * 2 + wn] = mhi;
        }
    }
    __syncthreads();
    if (tid < BM) {
        s_rowmax[tid] = fmaxf(s_red[tid * 2 + 0], s_red[tid * 2 + 1]);
    }
    __syncthreads();
#pragma unroll
    for (int mi = 0; mi < 4; mi++) {
        int rlo = wm * 64 + mi * 16 + (lane >> 2);
        int rhi = rlo + 8;
        float Mlo = s_rowmax[rlo], Mhi = s_rowmax[rhi];
        float slo = 0.f, shi = 0.f;
#pragma unroll
        for (int ni = 0; ni < 8; ni++) {
            slo += __expf(acc[mi][ni][0] - Mlo) + __expf(acc[mi][ni][1] - Mlo);
            shi += __expf(acc[mi][ni][2] - Mhi) + __expf(acc[mi][ni][3] - Mhi);
        }
#pragma unroll
        for (int o = 1; o < 4; o <<= 1) {
            slo += __shfl_xor_sync(0xffffffffu, slo, o);
            shi += __shfl_xor_sync(0xffffffffu, shi, o);
        }
        if ((lane & 3) == 0) {
            s_red[rlo * 2 + wn] = slo;
            s_red[rhi * 2 + wn] = shi;
        }
    }
    __syncthreads();
    if (tid < BM) {
        float s = s_red[tid * 2 + 0] + s_red[tid * 2 + 1];
        g_pmax[(size_t)nt * Mtot + m0 + tid] = s_rowmax[tid];
        g_psum[(size_t)nt * Mtot + m0 + tid] = s;
    }
}

// ----------------------------------------------------------------------------
// Coalesced logZ combine: 1 block per 32 tokens, 1024 threads (32 nt-slices x
// 32 tokens). Each 32-thread group reads a full 128B line. Online LSE merge.
// grid = 128.
// ----------------------------------------------------------------------------
__global__ __launch_bounds__(1024) void reduce_lz_kernel()
{
    __shared__ float s_mx[32][32];
    __shared__ float s_sv[32][32];
    const int tid = threadIdx.x;
    const int tg  = tid >> 5;            // nt-slice 0..31
    const int ml  = tid & 31;            // token within group
    const int m   = blockIdx.x * 32 + ml;

#pragma unroll
    for (int mat = 0; mat < 2; mat++) {
        const int base = mat * NT_PER;
        float mx = -1e30f, sv = 0.f;
        for (int nt = tg; nt < NT_PER; nt += 32) {
            const float p  = g_pmax[(size_t)(base + nt) * Mtot + m];
            const float ps = g_psum[(size_t)(base + nt) * Mtot + m];
            const float nm = fmaxf(mx, p);
            sv = sv * __expf(mx - nm) + ps * __expf(p - nm);
            mx = nm;
        }
        s_mx[tg][ml] = mx;
        s_sv[tg][ml] = sv;
        __syncthreads();
        if (tid < 32) {
            float M = -1e30f, S = 0.f;
#pragma unroll
            for (int g = 0; g < 32; g++) {
                const float p = s_mx[g][tid], ps = s_sv[g][tid];
                const float nm = fmaxf(M, p);
                S = S * __expf(M - nm) + ps * __expf(p - nm);
                M = nm;
            }
            const float lz = M + logf(S);
            if (mat == 0) g_lzW[m] = lz; else g_lzR[m] = lz;
        }
        __syncthreads();
    }
}

// ----------------------------------------------------------------------------
// Final DPO scalar. one block of 512; shuffle-based reductions (1 sync/batch).
// ----------------------------------------------------------------------------
__global__ __launch_bounds__(512) void final_kernel(const void* __restrict__ y,
                                                    float* __restrict__ out)
{
    __shared__ float s_p[16], s_r[16], s_c[16];
    __shared__ float pav[8], rav[8];
    const int tid  = threadIdx.x;
    const int warp = tid >> 5, lane = tid & 31;
    const int is64 = y_is64(y);

    for (int b = 0; b < 8; b++) {
        const int m = b * 512 + tid;
        const int yv = get_label(y, m, is64);
        const bool v = (yv != -100);
        float p = v ? (g_tokW[m] - g_lzW[m]) : 0.f;
        float r = v ? (g_tokR[m] - g_lzR[m]) : 0.f;
        float c = v ? 1.f : 0.f;
#pragma unroll
        for (int o = 16; o > 0; o >>= 1) {
            p += __shfl_xor_sync(0xffffffffu, p, o);
            r += __shfl_xor_sync(0xffffffffu, r, o);
            c += __shfl_xor_sync(0xffffffffu, c, o);
        }
        if (lane == 0) { s_p[warp] = p; s_r[warp] = r; s_c[warp] = c; }
        __syncthreads();
        if (tid == 0) {
            float ps = 0.f, rs = 0.f, cs = 0.f;
#pragma unroll
            for (int w = 0; w < 16; w++) { ps += s_p[w]; rs += s_r[w]; cs += s_c[w]; }
            pav[b] = ps / cs;
            rav[b] = rs / cs;
        }
        __syncthreads();
    }
    if (tid == 0) {
        float loss = 0.f;
#pragma unroll
        for (int i = 0; i < 4; i++) {
            float z = 0.1f * ((pav[i] - rav[i]) - (pav[i + 4] - rav[i + 4]));
            loss += log1pf(expf(-z));
        }
        out[0] = loss * 0.25f;
    }
}

// ----------------------------------------------------------------------------
extern "C" void kernel_launch(void* const* d_in, const int* in_sizes, int n_in,
                              void* d_out, int out_size)
{
    const float* x = nullptr;
    const void*  y = nullptr;
    const float* Wm[2] = {nullptr, nullptr};
    int wcount = 0;
    for (int i = 0; i < n_in; i++) {
        if (in_sizes[i] == 16777216)                          x = (const float*)d_in[i];
        else if (in_sizes[i] == 4096 || in_sizes[i] == 8192)  y = d_in[i];
        else if (wcount < 2)                                  Wm[wcount++] = (const float*)d_in[i];
    }
    if (!x)      x     = (const float*)d_in[0];
    if (!y)      y     = d_in[1];
    if (!Wm[0])  Wm[0] = (const float*)d_in[2];
    if (!Wm[1])  Wm[1] = (const float*)d_in[3];
    const float* W    = Wm[0];
    const float* refW = Wm[1];

    cudaFuncSetAttribute(lse_kernel, cudaFuncAttributeMaxDynamicSharedMemorySize, DSMEM);

    convert_tok_kernel<<<CONV_BLOCKS + TOK_BLOCKS, 256>>>(x, W, refW, y);

    dim3 grid(Mtot / BM, NT_TOT);   // (32 [fast: x L2-resident], 500)
    lse_kernel<<<grid, THREADS, DSMEM>>>();

    reduce_lz_kernel<<<Mtot / 32, 1024>>>();
    final_kernel<<<1, 512>>>(y, (float*)d_out);
}

// round 16
// speedup vs baseline: 1.1315x; 1.0028x over previous
#include <cuda_runtime.h>
#include <cuda_bf16.h>
#include <cstdint>

// ----------------------------------------------------------------------------
// DPO loss on GB300 (sm_103 base target — legacy bf16 HMMA, rt=8 ceiling).
// Round 16: champion + batch-parallel final_kernel (ballot dtype detect,
// 16 warps over 8 batches, single sync). All other kernels byte-identical.
// ----------------------------------------------------------------------------

#define BM 128
#define BN 128
#define KC 64                 // K elems per stage: 128B rows (SW128 swizzle)
#define NSTAGE 3
#define THREADS 128

static constexpr int Hdim   = 4096;
static constexpr int Mtot   = 4096;          // 8*512 tokens
static constexpr int Vdim   = 32000;
static constexpr int NT_PER = Vdim / BN;     // 250 N-tiles per matrix
static constexpr int NT_TOT = 2 * NT_PER;    // 500
static constexpr int NKT    = Hdim / KC;     // 64 k-chunks

static constexpr int A_BYTES  = BM * 128;    // 16 KB
static constexpr int B_BYTES  = BN * 128;    // 16 KB
static constexpr int STAGE_B  = A_BYTES + B_BYTES;          // 32 KB
static constexpr int DSMEM    = 1024 + NSTAGE * STAGE_B;    // ~97 KB

// ---------------- scratch (allocation-free __device__ globals) ----------------
__device__ __nv_bfloat16 g_xbf[(size_t)Mtot * Hdim];   //  33.5 MB
__device__ __nv_bfloat16 g_wbf[(size_t)Vdim * Hdim];   // 262 MB
__device__ __nv_bfloat16 g_rbf[(size_t)Vdim * Hdim];   // 262 MB
__device__ float g_pmax[NT_TOT * Mtot];
__device__ float g_psum[NT_TOT * Mtot];
__device__ float g_tokW[Mtot];
__device__ float g_tokR[Mtot];
__device__ float g_lzW[Mtot];
__device__ float g_lzR[Mtot];

__device__ __forceinline__ uint32_t smem_u32(const void* p) {
    return (uint32_t)__cvta_generic_to_shared(p);
}
__device__ __forceinline__ void cp_async16(uint32_t dst, const void* src) {
    asm volatile("cp.async.cg.shared.global [%0], [%1], 16;\n" :: "r"(dst), "l"(src));
}
#define SWZ(x) ((x) ^ (((x) >> 3) & 0x70))

// Inline y-dtype detection (serial form, used by tok blocks where it's
// off the critical path): int64 labels have high word 0 / -1.
__device__ __forceinline__ int y_is64(const void* y) {
    const int* y32 = (const int*)y;
    int is64 = 1;
#pragma unroll 8
    for (int i = 0; i < 64; i++) {
        int hi = y32[2 * i + 1];
        if (hi != 0 && hi != -1) { is64 = 0; break; }
    }
    return is64;
}
__device__ __forceinline__ int get_label(const void* y, int m, int is64) {
    if (is64) return (int)((const long long*)y)[m];
    return ((const int*)y)[m];
}

// ----------------------------------------------------------------------------
// Fused: fp32 -> bf16 convert (blocks 0..4095) + exact token logits (blocks
// 4096..4607; 8 warps x 1 token each = 4096 tokens).
// ----------------------------------------------------------------------------
static constexpr size_t N8_X = (size_t)Mtot * Hdim / 8;
static constexpr size_t N8_W = (size_t)Vdim * Hdim / 8;
static constexpr size_t N8_TOT = N8_X + 2 * N8_W;
static constexpr int CONV_BLOCKS = 4096;
static constexpr int TOK_BLOCKS  = Mtot / 8;   // 512

__global__ __launch_bounds__(256) void convert_tok_kernel(
    const float* __restrict__ x, const float* __restrict__ W,
    const float* __restrict__ R, const void* __restrict__ y)
{
    if (blockIdx.x < CONV_BLOCKS) {
        size_t i = (size_t)blockIdx.x * blockDim.x + threadIdx.x;
        const size_t stride = (size_t)CONV_BLOCKS * blockDim.x;
        for (; i < N8_TOT; i += stride) {
            const float* src;
            __nv_bfloat16* dst;
            size_t j;
            if (i < N8_X)               { src = x; dst = g_xbf; j = i; }
            else if (i < N8_X + N8_W)   { src = W; dst = g_wbf; j = i - N8_X; }
            else                        { src = R; dst = g_rbf; j = i - N8_X - N8_W; }
            const float4* s = reinterpret_cast<const float4*>(src) + 2 * j;
            float4 a = s[0], b = s[1];
            __nv_bfloat162 o[4] = {
                __floats2bfloat162_rn(a.x, a.y), __floats2bfloat162_rn(a.z, a.w),
                __floats2bfloat162_rn(b.x, b.y), __floats2bfloat162_rn(b.z, b.w)};
            *reinterpret_cast<uint4*>(dst + j * 8) = *reinterpret_cast<const uint4*>(o);
        }
    } else {
        // token-logit blocks: one warp per token, fp32 exact
        const int blk  = blockIdx.x - CONV_BLOCKS;      // 0..511
        const int warp = threadIdx.x >> 5, lane = threadIdx.x & 31;
        const int m = blk * 8 + warp;
        const int is64 = y_is64(y);
        int idx = get_label(y, m, is64);
        if (idx < 0 || idx >= Vdim) idx = 0;            // defensive clamp
        const float4* xr = reinterpret_cast<const float4*>(x + (size_t)m   * Hdim);
        const float4* wr = reinterpret_cast<const float4*>(W + (size_t)idx * Hdim);
        const float4* rr = reinterpret_cast<const float4*>(R + (size_t)idx * Hdim);
        float sw = 0.f, sr = 0.f;
        for (int j = lane; j < Hdim / 4; j += 32) {
            float4 a = xr[j], b = wr[j], c = rr[j];
            sw += a.x * b.x + a.y * b.y + a.z * b.z + a.w * b.w;
            sr += a.x * c.x + a.y * c.y + a.z * c.z + a.w * c.w;
        }
#pragma unroll
        for (int o = 16; o > 0; o >>= 1) {
            sw += __shfl_xor_sync(0xffffffffu, sw, o);
            sr += __shfl_xor_sync(0xffffffffu, sr, o);
        }
        if (lane == 0) { g_tokW[m] = sw; g_tokR[m] = sr; }
    }
}

// ----------------------------------------------------------------------------
// Main GEMM + online LSE epilogue. grid=(32 mt [fast], 500 nt), block=128.
// 4 warps in a 2x2 (M x N) grid; each warp computes 64x64. (champion mainloop)
// ----------------------------------------------------------------------------
__global__ __launch_bounds__(THREADS, 2) void lse_kernel()
{
    extern __shared__ char dsm[];
    const uint32_t raw  = smem_u32(dsm);
    const uint32_t stg  = (raw + 1023) & ~1023u;   // 1024-aligned

    __shared__ float s_red[BM * 2];
    __shared__ float s_rowmax[BM];

    const int tid  = threadIdx.x;
    const int warp = tid >> 5, lane = tid & 31;
    const int wm   = warp >> 1, wn = warp & 1;     // 2 x 2 warp grid

    const int mt = blockIdx.x, nt = blockIdx.y;
    const int m0 = mt * BM;
    const int n0 = (nt < NT_PER ? nt : nt - NT_PER) * BN;
    const __nv_bfloat16* asrc = g_xbf + (size_t)m0 * Hdim;
    const __nv_bfloat16* bsrc = ((nt < NT_PER) ? g_wbf : g_rbf) + (size_t)n0 * Hdim;

    float acc[4][8][4];            // 128 fp32 accumulators / thread
#pragma unroll
    for (int i = 0; i < 4; i++)
#pragma unroll
        for (int j = 0; j < 8; j++)
#pragma unroll
            for (int c = 0; c < 4; c++) acc[i][j][c] = 0.f;

    auto load_stage = [&](int slot, int kt) {
        const uint32_t a_base = stg + slot * STAGE_B;
        const uint32_t b_base = a_base + A_BYTES;
        const int k0 = kt * KC;
#pragma unroll
        for (int i = 0; i < 8; i++) {
            int id  = tid + i * THREADS;      // 0..1023
            int row = id >> 3, c = id & 7;    // 128 rows x 8 chunks
            cp_async16(a_base + SWZ(row * 128 + c * 16),
                       asrc + (size_t)row * Hdim + k0 + c * 8);
            cp_async16(b_base + SWZ(row * 128 + c * 16),
                       bsrc + (size_t)row * Hdim + k0 + c * 8);
        }
        asm volatile("cp.async.commit_group;" ::: "memory");
    };

    auto compute = [&](int slot) {
        const uint32_t a_base = stg + slot * STAGE_B;
        const uint32_t b_base = a_base + A_BYTES;
#pragma unroll
        for (int ks = 0; ks < 4; ks++) {       // 4 x K=16 inside the 64 chunk
            uint32_t af[4][4], bf[8][2];
            const int arow = wm * 64 + (lane & 15);
            const int asel = (lane >> 4) & 1;
#pragma unroll
            for (int mi = 0; mi < 4; mi++) {
                uint32_t addr = a_base +
                    SWZ((uint32_t)(arow + mi * 16) * 128 + ks * 32 + asel * 16);
                asm volatile("ldmatrix.sync.aligned.m8n8.x4.shared.b16 {%0,%1,%2,%3}, [%4];"
                             : "=r"(af[mi][0]), "=r"(af[mi][1]),
                               "=r"(af[mi][2]), "=r"(af[mi][3])
                             : "r"(addr));
            }
            // B: x4 over pairs of 8-col groups.
#pragma unroll
            for (int np = 0; np < 4; np++) {
                const uint32_t brow = wn * 64 + np * 16 +
                                      ((lane >> 4) << 3) + (lane & 7);
                const uint32_t bsel = (lane >> 3) & 1;
                uint32_t addr = b_base + SWZ(brow * 128 + ks * 32 + bsel * 16);
                asm volatile("ldmatrix.sync.aligned.m8n8.x4.shared.b16 {%0,%1,%2,%3}, [%4];"
                             : "=r"(bf[2 * np][0]), "=r"(bf[2 * np][1]),
                               "=r"(bf[2 * np + 1][0]), "=r"(bf[2 * np + 1][1])
                             : "r"(addr));
            }
#pragma unroll
            for (int mi = 0; mi < 4; mi++)
#pragma unroll
                for (int ni = 0; ni < 8; ni++)
                    asm volatile(
                        "mma.sync.aligned.m16n8k16.row.col.f32.bf16.bf16.f32 "
                        "{%0,%1,%2,%3}, {%4,%5,%6,%7}, {%8,%9}, {%0,%1,%2,%3};"
                        : "+f"(acc[mi][ni][0]), "+f"(acc[mi][ni][1]),
                          "+f"(acc[mi][ni][2]), "+f"(acc[mi][ni][3])
                        : "r"(af[mi][0]), "r"(af[mi][1]), "r"(af[mi][2]), "r"(af[mi][3]),
                          "r"(bf[ni][0]), "r"(bf[ni][1]));
        }
    };

    // prologue: fill NSTAGE-1 stages
    load_stage(0, 0);
    load_stage(1, 1);

    for (int kt = 0; kt < NKT; kt++) {
        const int slot = kt % NSTAGE;
        if (kt + 2 < NKT) {
            asm volatile("cp.async.wait_group 1;" ::: "memory");
        } else {
            asm volatile("cp.async.wait_group 0;" ::: "memory");
        }
        __syncthreads();
        if (kt + 2 < NKT) load_stage((kt + 2) % NSTAGE, kt + 2);
        compute(slot);
    }

    // ---- fused epilogue: per-token max / sumexp over this 128-col tile ----
    const float NEG = -1e30f;
#pragma unroll
    for (int mi = 0; mi < 4; mi++) {
        float mlo = NEG, mhi = NEG;
#pragma unroll
        for (int ni = 0; ni < 8; ni++) {
            mlo = fmaxf(mlo, fmaxf(acc[mi][ni][0], acc[mi][ni][1]));
            mhi = fmaxf(mhi, fmaxf(acc[mi][ni][2], acc[mi][ni][3]));
        }
#pragma unroll
        for (int o = 1; o < 4; o <<= 1) {
            mlo = fmaxf(mlo, __shfl_xor_sync(0xffffffffu, mlo, o));
            mhi = fmaxf(mhi, __shfl_xor_sync(0xffffffffu, mhi, o));
        }
        if ((lane & 3) == 0) {
            int rlo = wm * 64 + mi * 16 + (lane >> 2);
            s_red[rlo * 2 + wn]       = mlo;
            s_red[(rlo + 8) * 2 + wn] = mhi;
        }
    }
    __syncthreads();
    if (tid < BM) {
        s_rowmax[tid] = fmaxf(s_red[tid * 2 + 0], s_red[tid * 2 + 1]);
    }
    __syncthreads();
#pragma unroll
    for (int mi = 0; mi < 4; mi++) {
        int rlo = wm * 64 + mi * 16 + (lane >> 2);
        int rhi = rlo + 8;
        float Mlo = s_rowmax[rlo], Mhi = s_rowmax[rhi];
        float slo = 0.f, shi = 0.f;
#pragma unroll
        for (int ni = 0; ni < 8; ni++) {
            slo += __expf(acc[mi][ni][0] - Mlo) + __expf(acc[mi][ni][1] - Mlo);
            shi += __expf(acc[mi][ni][2] - Mhi) + __expf(acc[mi][ni][3] - Mhi);
        }
#pragma unroll
        for (int o = 1; o < 4; o <<= 1) {
            slo += __shfl_xor_sync(0xffffffffu, slo, o);
            shi += __shfl_xor_sync(0xffffffffu, shi, o);
        }
        if ((lane & 3) == 0) {
            s_red[rlo * 2 + wn] = slo;
            s_red[rhi * 2 + wn] = shi;
        }
    }
    __syncthreads();
    if (tid < BM) {
        float s = s_red[tid * 2 + 0] + s_red[tid * 2 + 1];
        g_pmax[(size_t)nt * Mtot + m0 + tid] = s_rowmax[tid];
        g_psum[(size_t)nt * Mtot + m0 + tid] = s;
    }
}

// ----------------------------------------------------------------------------
// Coalesced logZ combine: 1 block per 32 tokens, 1024 threads (32 nt-slices x
// 32 tokens). Each 32-thread group reads a full 128B line. Online LSE merge.
// grid = 128.
// ----------------------------------------------------------------------------
__global__ __launch_bounds__(1024) void reduce_lz_kernel()
{
    __shared__ float s_mx[32][32];
    __shared__ float s_sv[32][32];
    const int tid = threadIdx.x;
    const int tg  = tid >> 5;            // nt-slice 0..31
    const int ml  = tid & 31;            // token within group
    const int m   = blockIdx.x * 32 + ml;

#pragma unroll
    for (int mat = 0; mat < 2; mat++) {
        const int base = mat * NT_PER;
        float mx = -1e30f, sv = 0.f;
        for (int nt = tg; nt < NT_PER; nt += 32) {
            const float p  = g_pmax[(size_t)(base + nt) * Mtot + m];
            const float ps = g_psum[(size_t)(base + nt) * Mtot + m];
            const float nm = fmaxf(mx, p);
            sv = sv * __expf(mx - nm) + ps * __expf(p - nm);
            mx = nm;
        }
        s_mx[tg][ml] = mx;
        s_sv[tg][ml] = sv;
        __syncthreads();
        if (tid < 32) {
            float M = -1e30f, S = 0.f;
#pragma unroll
            for (int g = 0; g < 32; g++) {
                const float p = s_mx[g][tid], ps = s_sv[g][tid];
                const float nm = fmaxf(M, p);
                S = S * __expf(M - nm) + ps * __expf(p - nm);
                M = nm;
            }
            const float lz = M + logf(S);
            if (mat == 0) g_lzW[m] = lz; else g_lzR[m] = lz;
        }
        __syncthreads();
    }
}

// ----------------------------------------------------------------------------
// Final DPO scalar. One block of 512, batch-parallel:
//   warp w in [0,16): batch b = w/2, half h = w%2; each thread owns 8 tokens
//   (m = b*512 + h*256 + i*32 + lane). One sync; thread 0 combines + emits.
// Dtype detect via warp ballot (2 loads/lane instead of a 64-iter serial scan).
// ----------------------------------------------------------------------------
__global__ __launch_bounds__(512) void final_kernel(const void* __restrict__ y,
                                                    float* __restrict__ out)
{
    __shared__ float s_p[16], s_r[16], s_c[16];
    __shared__ int   s_is64;
    const int tid  = threadIdx.x;
    const int warp = tid >> 5, lane = tid & 31;

    // warp 0: ballot-based int64 signature check over the first 64 slots
    if (warp == 0) {
        const int* y32 = (const int*)y;
        int hi0 = y32[2 * lane + 1];
        int hi1 = y32[2 * (lane + 32) + 1];
        bool ok = (hi0 == 0 || hi0 == -1) && (hi1 == 0 || hi1 == -1);
        uint32_t vote = __ballot_sync(0xffffffffu, ok);
        if (lane == 0) s_is64 = (vote == 0xffffffffu);
    }
    __syncthreads();
    const int is64 = s_is64;

    // batch-parallel accumulation: 2 warps per batch, 8 tokens per thread
    const int b = warp >> 1, h = warp & 1;
    float p = 0.f, r = 0.f, c = 0.f;
#pragma unroll
    for (int i = 0; i < 8; i++) {
        const int m = b * 512 + h * 256 + i * 32 + lane;
        const int yv = get_label(y, m, is64);
        if (yv != -100) {
            p += g_tokW[m] - g_lzW[m];
            r += g_tokR[m] - g_lzR[m];
            c += 1.f;
        }
    }
#pragma unroll
    for (int o = 16; o > 0; o >>= 1) {
        p += __shfl_xor_sync(0xffffffffu, p, o);
        r += __shfl_xor_sync(0xffffffffu, r, o);
        c += __shfl_xor_sync(0xffffffffu, c, o);
    }
    if (lane == 0) { s_p[warp] = p; s_r[warp] = r; s_c[warp] = c; }
    __syncthreads();

    if (tid == 0) {
        float pav[8], rav[8];
#pragma unroll
        for (int bb = 0; bb < 8; bb++) {
            const float ps = s_p[2 * bb] + s_p[2 * bb + 1];
            const float rs = s_r[2 * bb] + s_r[2 * bb + 1];
            const float cs = s_c[2 * bb] + s_c[2 * bb + 1];
            pav[bb] = ps / cs;
            rav[bb] = rs / cs;
        }
        float loss = 0.f;
#pragma unroll
        for (int i = 0; i < 4; i++) {
            float z = 0.1f * ((pav[i] - rav[i]) - (pav[i + 4] - rav[i + 4]));
            loss += log1pf(expf(-z));
        }
        out[0] = loss * 0.25f;
    }
}

// ----------------------------------------------------------------------------
extern "C" void kernel_launch(void* const* d_in, const int* in_sizes, int n_in,
                              void* d_out, int out_size)
{
    const float* x = nullptr;
    const void*  y = nullptr;
    const float* Wm[2] = {nullptr, nullptr};
    int wcount = 0;
    for (int i = 0; i < n_in; i++) {
        if (in_sizes[i] == 16777216)                          x = (const float*)d_in[i];
        else if (in_sizes[i] == 4096 || in_sizes[i] == 8192)  y = d_in[i];
        else if (wcount < 2)                                  Wm[wcount++] = (const float*)d_in[i];
    }
    if (!x)      x     = (const float*)d_in[0];
    if (!y)      y     = d_in[1];
    if (!Wm[0])  Wm[0] = (const float*)d_in[2];
    if (!Wm[1])  Wm[1] = (const float*)d_in[3];
    const float* W    = Wm[0];
    const float* refW = Wm[1];

    cudaFuncSetAttribute(lse_kernel, cudaFuncAttributeMaxDynamicSharedMemorySize, DSMEM);

    convert_tok_kernel<<<CONV_BLOCKS + TOK_BLOCKS, 256>>>(x, W, refW, y);

    dim3 grid(Mtot / BM, NT_TOT);   // (32 [fast: x L2-resident], 500)
    lse_kernel<<<grid, THREADS, DSMEM>>>();

    reduce_lz_kernel<<<Mtot / 32, 1024>>>();
    final_kernel<<<1, 512>>>(y, (float*)d_out);
}